// round 9
// baseline (speedup 1.0000x reference)
#include <cuda_runtime.h>
#include <math.h>
#include <stdint.h>

// ---------------- problem constants ----------------
#define NT 20000
#define NC 200000
#define NF 40000
#define E_HC 200000
#define E_BT 200000
#define E_IS 80000
#define E_PT 80000
#define FH 256

// ---------------- scratch offsets (floats) ----------------
static constexpr size_t OFF_FEAT_T = 0;
static constexpr size_t OFF_FEAT_C = OFF_FEAT_T + (size_t)NT * 256;
static constexpr size_t OFF_FEAT_F = OFF_FEAT_C + (size_t)NC * 256;
static constexpr size_t OFF_XCT    = OFF_FEAT_F + (size_t)NF * 256;   // NT x 512
static constexpr size_t OFF_XCC    = OFF_XCT + (size_t)NT * 512;      // NC x 1024
static constexpr size_t OFF_XCF    = OFF_XCC + (size_t)NC * 1024;     // NF x 512
static constexpr size_t OFF_OT     = OFF_XCF + (size_t)NF * 512;      // zero region start
static constexpr size_t OFF_OF     = OFF_OT  + (size_t)NT * 256;
static constexpr size_t OFF_OC     = OFF_OF  + (size_t)NF * 256;      // merged hc+pt accumulator
static constexpr size_t OFF_SEG    = OFF_OC  + (size_t)NC * 256;      // 3,680,000 floats
static constexpr size_t ZERO_FLOATS = (size_t)NT * 256 + (size_t)NF * 256 + (size_t)NC * 256 + 3680000;
static constexpr size_t OFF_LOGIT  = OFF_SEG + 3680000;               // 560000*4
static constexpr size_t OFF_RLIN   = OFF_LOGIT + 2240000;             // 49152  (transposed [N,K])
static constexpr size_t OFF_ROUT   = OFF_RLIN + 49152;                // 196608 (transposed)
static constexpr size_t OFF_CAT0   = OFF_ROUT + 196608;               // [2048 x 64]  transposed
static constexpr size_t OFF_CAT1   = OFF_CAT0 + 131072;               // [2048 x 256] transposed
static constexpr size_t OFF_RXT    = OFF_CAT1 + 524288;               // rounded x_table
static constexpr size_t OFF_RXC    = OFF_RXT + (size_t)NT * 256;
static constexpr size_t OFF_RXF    = OFF_RXC + (size_t)NC * 256;
static constexpr size_t SCRATCH_TOTAL = OFF_RXF + (size_t)NF * 256;

__device__ float g_scratch[SCRATCH_TOTAL];

// ---------------- PTX helpers ----------------
__device__ __forceinline__ void cp_async16(void* dst, const void* src)
{
    uint32_t d = (uint32_t)__cvta_generic_to_shared(dst);
    asm volatile("cp.async.cg.shared.global [%0], [%1], 16;\n" :: "r"(d), "l"(src));
}
__device__ __forceinline__ void cp_commit() { asm volatile("cp.async.commit_group;\n" ::: "memory"); }
__device__ __forceinline__ void cp_wait0()  { asm volatile("cp.async.wait_group 0;\n" ::: "memory"); }
__device__ __forceinline__ void cp_wait1()  { asm volatile("cp.async.wait_group 1;\n" ::: "memory"); }

__device__ __forceinline__ uint32_t cvt_tf32(float x)
{
    uint32_t r; asm("cvt.rna.tf32.f32 %0, %1;" : "=r"(r) : "f"(x)); return r;
}
__device__ __forceinline__ float round_tf32(float x) { return __uint_as_float(cvt_tf32(x)); }

__device__ __forceinline__ void mma_tf32(float* c, const uint32_t* a, const uint32_t* b)
{
    asm volatile("mma.sync.aligned.m16n8k8.row.col.f32.tf32.tf32.f32 "
                 "{%0,%1,%2,%3}, {%4,%5,%6,%7}, {%8,%9}, {%0,%1,%2,%3};"
                 : "+f"(c[0]), "+f"(c[1]), "+f"(c[2]), "+f"(c[3])
                 : "r"(a[0]), "r"(a[1]), "r"(a[2]), "r"(a[3]), "r"(b[0]), "r"(b[1]));
}

__device__ __forceinline__ void ldsm_x4(uint32_t& r0, uint32_t& r1, uint32_t& r2, uint32_t& r3,
                                        uint32_t addr)
{
    asm volatile("ldmatrix.sync.aligned.m8n8.x4.shared.b16 {%0,%1,%2,%3}, [%4];"
                 : "=r"(r0), "=r"(r1), "=r"(r2), "=r"(r3) : "r"(addr));
}

__device__ __forceinline__ uint32_t fmax_key(float f)
{
    int i = __float_as_int(f);
    return (i >= 0) ? ((uint32_t)i | 0x80000000u) : ~(uint32_t)i;
}
__device__ __forceinline__ float fmax_unkey(uint32_t u)
{
    return (u & 0x80000000u) ? __int_as_float((int)(u & 0x7fffffffu))
                             : __int_as_float((int)~u);
}

// ---------------- grouped tf32 GEMM (ldmatrix fragments) ----------------
// A [M,K] row-major (pre-rounded tf32). B TRANSPOSED [N,K] row-major
// (pre-rounded). Both smem tiles are K-major rows padded to 36 floats.
struct GemmGroups {
    const float* A[3]; const float* B[3]; const float* bias[3]; float* C[3];
    int M[3]; int N[3];
    int maskX[3]; int shiftX[3];
    int blockStart[3];
    int K;
};

template<int ACT, int ROUND_OUT, int BN, int WARPS_M, int WARPS_N>
__global__ void __launch_bounds__(256, 2)
gemm_grouped(GemmGroups gg)
{
    constexpr int BM = 128, BK = 32;
    constexpr int BKP = 36;                 // row pad: 8 ldsm rows hit 8 distinct bank-quads
    constexpr int WM = BM / WARPS_M, WN = BN / WARPS_N;
    constexpr int MI = WM / 16, NI = WN / 8;
    constexpr int A_STAGE = BM * BKP;
    constexpr int B_STAGE = BN * BKP;
    constexpr int STAGES = 3;

    extern __shared__ float sm[];
    float* Asm = sm;
    float* Bsm = sm + STAGES * A_STAGE;
    const uint32_t AsmU = (uint32_t)__cvta_generic_to_shared(Asm);
    const uint32_t BsmU = (uint32_t)__cvta_generic_to_shared(Bsm);

    const int bid = blockIdx.x;
    const int g = (bid >= gg.blockStart[1]) + (bid >= gg.blockStart[2]);
    const int local = bid - gg.blockStart[g];
    const int tileX = local & gg.maskX[g];
    const int tileY = local >> gg.shiftX[g];

    const float* __restrict__ A = gg.A[g];
    const float* __restrict__ Bt = gg.B[g];
    const float* __restrict__ bias = gg.bias[g];
    float* __restrict__ C = gg.C[g];
    const int M = gg.M[g], N = gg.N[g], K = gg.K;
    const int rowBase = tileY * BM;
    const int colBase = tileX * BN;

    const int tid  = threadIdx.x;
    const int lane = tid & 31;
    const int warp = tid >> 5;
    const int gq   = lane >> 2;
    const int tig  = lane & 3;
    const int warpM = warp % WARPS_M;
    const int warpN = warp / WARPS_M;

    // ldmatrix per-thread source row/col (A: mat&1->+8row, mat&2->+4col;
    //                                    B: mat&1->+4col, mat&2->+8row)
    const int aRow = (lane & 7) + (((lane >> 3) & 1) << 3);
    const int aCol = ((lane >> 4) & 1) << 2;
    const int bRow = (lane & 7) + (((lane >> 4) & 1) << 3);
    const int bCol = ((lane >> 3) & 1) << 2;

    float acc[MI][NI][4];
#pragma unroll
    for (int mi = 0; mi < MI; mi++)
#pragma unroll
        for (int ni = 0; ni < NI; ni++)
#pragma unroll
            for (int q = 0; q < 4; q++) acc[mi][ni][q] = 0.f;

    auto load_tile = [&](int t, int s) {
        // A tile: BM x BK
#pragma unroll
        for (int i = 0; i < 4; i++) {
            int li = tid + i * 256;
            int m = li >> 3;
            int k4 = (li & 7) << 2;
            int gm = rowBase + m;
            if (gm >= M) gm = M - 1;
            cp_async16(Asm + s * A_STAGE + m * BKP + k4,
                       A + (size_t)gm * K + t * BK + k4);
        }
        // B tile: BN rows of Bt, each BK floats (K-contiguous)
#pragma unroll
        for (int i = 0; i < (BN * BK) / 1024; i++) {
            int li = tid + i * 256;
            int n = li >> 3;
            int k4 = (li & 7) << 2;
            cp_async16(Bsm + s * B_STAGE + n * BKP + k4,
                       Bt + (size_t)(colBase + n) * K + t * BK + k4);
        }
        cp_commit();
    };

    const int nT = K / BK;
    load_tile(0, 0);
    if (nT > 1) load_tile(1, 1);

    for (int t = 0; t < nT; t++) {
        if (t + 1 < nT) cp_wait1(); else cp_wait0();
        __syncthreads();
        if (t + 2 < nT) load_tile(t + 2, (t + 2) % STAGES);

        const uint32_t asb = AsmU + (uint32_t)((t % STAGES) * A_STAGE) * 4u;
        const uint32_t bsb = BsmU + (uint32_t)((t % STAGES) * B_STAGE) * 4u;
#pragma unroll
        for (int k8 = 0; k8 < BK / 8; k8++) {
            const int kk = k8 * 8;
            uint32_t a[MI][4], b[NI][2];
#pragma unroll
            for (int mi = 0; mi < MI; mi++) {
                uint32_t ad = asb + (uint32_t)((warpM * WM + mi * 16 + aRow) * BKP + kk + aCol) * 4u;
                ldsm_x4(a[mi][0], a[mi][1], a[mi][2], a[mi][3], ad);
            }
#pragma unroll
            for (int ni2 = 0; ni2 < NI / 2; ni2++) {
                uint32_t bd = bsb + (uint32_t)((warpN * WN + ni2 * 16 + bRow) * BKP + kk + bCol) * 4u;
                ldsm_x4(b[2 * ni2][0], b[2 * ni2][1], b[2 * ni2 + 1][0], b[2 * ni2 + 1][1], bd);
            }
#pragma unroll
            for (int mi = 0; mi < MI; mi++)
#pragma unroll
                for (int ni = 0; ni < NI; ni++)
                    mma_tf32(acc[mi][ni], a[mi], b[ni]);
        }
    }

#pragma unroll
    for (int mi = 0; mi < MI; mi++) {
        int row0 = rowBase + warpM * WM + mi * 16 + gq;
#pragma unroll
        for (int ni = 0; ni < NI; ni++) {
            int col = colBase + warpN * WN + ni * 8 + tig * 2;
            float bx = 0.f, by = 0.f;
            if (bias) { bx = bias[col]; by = bias[col + 1]; }
            float2 v;
            v.x = acc[mi][ni][0] + bx;
            v.y = acc[mi][ni][1] + by;
            if (ACT == 1) {
                v.x = v.x > 0.f ? v.x : 0.01f * v.x;
                v.y = v.y > 0.f ? v.y : 0.01f * v.y;
            }
            if (ROUND_OUT) { v.x = round_tf32(v.x); v.y = round_tf32(v.y); }
            if (row0 < M) *(float2*)(C + (size_t)row0 * N + col) = v;
            v.x = acc[mi][ni][2] + bx;
            v.y = acc[mi][ni][3] + by;
            if (ACT == 1) {
                v.x = v.x > 0.f ? v.x : 0.01f * v.x;
                v.y = v.y > 0.f ? v.y : 0.01f * v.y;
            }
            if (ROUND_OUT) { v.x = round_tf32(v.x); v.y = round_tf32(v.y); }
            if (row0 + 8 < M) *(float2*)(C + (size_t)(row0 + 8) * N + col) = v;
        }
    }
}

#define SMEM_BN128 (3 * (128*36 + 128*36) * 4)   // 110592
#define SMEM_BN64  (3 * (128*36 + 64*36)  * 4)   // 82944

// ---------------- weight prep: round + transpose + concat ----------------
// catT[j][k], j = output column (0..2047), k = 0..K-1
__device__ float catT_src(int j, int k, int K, const float* Wl, const float* Wr)
{
    if (j < 512) {
        return (j < 256) ? Wl[(size_t)k * 256 + j]
                         : Wr[((size_t)K + k) * 256 + (j - 256)];
    }
    if (j < 1536) {
        int jj = j - 512;
        int c = jj >> 8, col = jj & 255;
        const float* p = (c == 0) ? Wr
                       : (c == 1) ? Wl + (size_t)1 * K * 256
                       : (c == 2) ? Wl + (size_t)2 * K * 256
                                  : Wr + (size_t)3 * K * 256;
        return p[(size_t)k * 256 + col];
    }
    int jj = j - 1536;
    return (jj < 256) ? Wr[((size_t)2 * K + k) * 256 + jj]
                      : Wl[((size_t)3 * K + k) * 256 + (jj - 256)];
}

__global__ void prep_weights(const float* __restrict__ lw, const float* __restrict__ ow,
                             const float* __restrict__ wl0, const float* __restrict__ wr0,
                             const float* __restrict__ wl1, const float* __restrict__ wr1,
                             float* __restrict__ rlinT, float* __restrict__ routT,
                             float* __restrict__ cat0T, float* __restrict__ cat1T)
{
    int i = blockIdx.x * blockDim.x + threadIdx.x;
    if (i < 49152) {            // lin: [3][64 n][256 k] <- lw[3][256 k][64 n]
        int m = i >> 14, r = i & 16383, n = r >> 8, k = r & 255;
        rlinT[i] = round_tf32(lw[m * 16384 + k * 64 + n]);
        return;
    }
    i -= 49152;
    if (i < 196608) {           // out: [3][256 n][256 k] <- ow[3][256 k][256 n]
        int m = i >> 16, r = i & 65535, n = r >> 8, k = r & 255;
        routT[i] = round_tf32(ow[m * 65536 + k * 256 + n]);
        return;
    }
    i -= 196608;
    if (i < 131072) {           // cat0T: [2048][64]
        int j = i >> 6, k = i & 63;
        cat0T[i] = round_tf32(catT_src(j, k, 64, wl0, wr0));
        return;
    }
    i -= 131072;
    if (i < 524288) {           // cat1T: [2048][256]
        int j = i >> 8, k = i & 255;
        cat1T[i] = round_tf32(catT_src(j, k, 256, wl1, wr1));
    }
}

// round raw x inputs to tf32 (float4-wide)
__global__ void round_inputs(const float* __restrict__ xt, const float* __restrict__ xc,
                             const float* __restrict__ xf,
                             float* __restrict__ rt, float* __restrict__ rc, float* __restrict__ rf)
{
    const int t4 = NT * 64, c4 = NC * 64, f4 = NF * 64;
    int i = blockIdx.x * blockDim.x + threadIdx.x;
    const float4* src; float4* dst; int j;
    if (i < t4) { src = (const float4*)xt; dst = (float4*)rt; j = i; }
    else if ((j = i - t4) < c4) { src = (const float4*)xc; dst = (float4*)rc; }
    else if ((j = i - t4 - c4) < f4) { src = (const float4*)xf; dst = (float4*)rf; }
    else return;
    float4 v = src[j];
    v.x = round_tf32(v.x); v.y = round_tf32(v.y);
    v.z = round_tf32(v.z); v.w = round_tf32(v.w);
    dst[j] = v;
}

// ---------------- batched edge kernels (unchanged from R8) ----------------
struct EdgeB {
    const int* src[4]; const int* dst[4];
    const float* xl[4]; const float* xr[4];
    int xls[4], xrs[4];
    const float* att;
    float* logit[4];
    uint32_t* segm[4]; float* segd[4];
    float* out[4];
    int eStart[5];
};

__global__ void edge_logits_b(EdgeB eb)
{
    int w = blockIdx.x * 8 + (threadIdx.x >> 5);
    if (w >= eb.eStart[4]) return;
    int c = (w >= eb.eStart[2]) ? ((w >= eb.eStart[3]) ? 3 : 2)
                                : ((w >= eb.eStart[1]) ? 1 : 0);
    int e = w - eb.eStart[c];
    int lane = threadIdx.x & 31;
    int s = eb.src[c][e], d = eb.dst[c][e];
    const float4* pl = (const float4*)(eb.xl[c] + (size_t)s * eb.xls[c]) + lane * 2;
    const float4* pr = (const float4*)(eb.xr[c] + (size_t)d * eb.xrs[c]) + lane * 2;
    const float4* pa = (const float4*)(eb.att + c * 256) + lane * 2;
    float sum = 0.f;
#pragma unroll
    for (int i = 0; i < 2; i++) {
        float4 l4 = pl[i], r4 = pr[i], a4 = pa[i];
        float v;
        v = l4.x + r4.x; v = v > 0.f ? v : 0.2f * v; sum += v * a4.x;
        v = l4.y + r4.y; v = v > 0.f ? v : 0.2f * v; sum += v * a4.y;
        v = l4.z + r4.z; v = v > 0.f ? v : 0.2f * v; sum += v * a4.z;
        v = l4.w + r4.w; v = v > 0.f ? v : 0.2f * v; sum += v * a4.w;
    }
    sum += __shfl_xor_sync(0xffffffffu, sum, 1);
    sum += __shfl_xor_sync(0xffffffffu, sum, 2);
    sum += __shfl_xor_sync(0xffffffffu, sum, 4);
    if ((lane & 7) == 0) {
        int h = lane >> 3;
        eb.logit[c][(size_t)e * 4 + h] = sum;
        atomicMax(eb.segm[c] + (size_t)d * 4 + h, fmax_key(sum));
    }
}

__global__ void edge_exp_b(EdgeB eb)
{
    int i = blockIdx.x * blockDim.x + threadIdx.x;
    if (i >= eb.eStart[4]) return;
    int c = (i >= eb.eStart[2]) ? ((i >= eb.eStart[3]) ? 3 : 2)
                                : ((i >= eb.eStart[1]) ? 1 : 0);
    int e = i - eb.eStart[c];
    int d = eb.dst[c][e];
    float4 lg = ((const float4*)eb.logit[c])[e];
    uint4 mk = ((const uint4*)eb.segm[c])[d];
    float4 z;
    z.x = expf(lg.x - fmax_unkey(mk.x));
    z.y = expf(lg.y - fmax_unkey(mk.y));
    z.z = expf(lg.z - fmax_unkey(mk.z));
    z.w = expf(lg.w - fmax_unkey(mk.w));
    ((float4*)eb.logit[c])[e] = z;
    asm volatile("red.global.add.v4.f32 [%0], {%1,%2,%3,%4};"
                 :: "l"(eb.segd[c] + (size_t)d * 4), "f"(z.x), "f"(z.y), "f"(z.z), "f"(z.w)
                 : "memory");
}

__global__ void edge_scatter_b(EdgeB eb)
{
    int w = blockIdx.x * 8 + (threadIdx.x >> 5);
    if (w >= eb.eStart[4]) return;
    int c = (w >= eb.eStart[2]) ? ((w >= eb.eStart[3]) ? 3 : 2)
                                : ((w >= eb.eStart[1]) ? 1 : 0);
    int e = w - eb.eStart[c];
    int lane = threadIdx.x & 31;
    int s = eb.src[c][e], d = eb.dst[c][e];
    int h = lane >> 3;
    float alpha = eb.logit[c][(size_t)e * 4 + h] / eb.segd[c][(size_t)d * 4 + h];
    const float4* pl = (const float4*)(eb.xl[c] + (size_t)s * eb.xls[c]) + lane * 2;
    float* po = eb.out[c] + (size_t)d * FH + lane * 8;
#pragma unroll
    for (int i = 0; i < 2; i++) {
        float4 v = pl[i];
        v.x *= alpha; v.y *= alpha; v.z *= alpha; v.w *= alpha;
        asm volatile("red.global.add.v4.f32 [%0], {%1,%2,%3,%4};"
                     :: "l"(po + i * 4), "f"(v.x), "f"(v.y), "f"(v.z), "f"(v.w)
                     : "memory");
    }
}

// ---------------- fused ELU / combine with bias ----------------
__device__ __forceinline__ float eluf(float x) { return x > 0.f ? x : expm1f(x); }

__global__ void elu_comb(const float* __restrict__ ot, const float* __restrict__ oc,
                         const float* __restrict__ of,
                         const float* __restrict__ b_hc, const float* __restrict__ b_bt,
                         const float* __restrict__ b_is, const float* __restrict__ b_pt,
                         float* __restrict__ ft, float* __restrict__ fc, float* __restrict__ ff)
{
    const int nT4 = NT * 64, nC4 = NC * 64, nF4 = NF * 64;
    int i = blockIdx.x * blockDim.x + threadIdx.x;
    if (i < nT4) {
        float4 v = ((const float4*)ot)[i];
        float4 b = ((const float4*)b_bt)[i & 63];
        v.x = round_tf32(eluf(v.x + b.x)); v.y = round_tf32(eluf(v.y + b.y));
        v.z = round_tf32(eluf(v.z + b.z)); v.w = round_tf32(eluf(v.w + b.w));
        ((float4*)ft)[i] = v;
    } else if (i < nT4 + nC4) {
        int j = i - nT4;
        float4 x = ((const float4*)oc)[j];
        float4 bh = ((const float4*)b_hc)[j & 63];
        float4 bp = ((const float4*)b_pt)[j & 63];
        float4 v;
        v.x = round_tf32(eluf(0.5f * (x.x + bh.x + bp.x)));
        v.y = round_tf32(eluf(0.5f * (x.y + bh.y + bp.y)));
        v.z = round_tf32(eluf(0.5f * (x.z + bh.z + bp.z)));
        v.w = round_tf32(eluf(0.5f * (x.w + bh.w + bp.w)));
        ((float4*)fc)[j] = v;
    } else if (i < nT4 + nC4 + nF4) {
        int j = i - nT4 - nC4;
        float4 v = ((const float4*)of)[j];
        float4 b = ((const float4*)b_is)[j & 63];
        v.x = round_tf32(eluf(v.x + b.x)); v.y = round_tf32(eluf(v.y + b.y));
        v.z = round_tf32(eluf(v.z + b.z)); v.w = round_tf32(eluf(v.w + b.w));
        ((float4*)ff)[j] = v;
    }
}

// ---------------- host orchestration ----------------
extern "C" void kernel_launch(void* const* d_in, const int* in_sizes, int n_in,
                              void* d_out, int out_size)
{
    (void)in_sizes; (void)n_in; (void)out_size;
    const float* x_table  = (const float*)d_in[0];
    const float* x_column = (const float*)d_in[1];
    const float* x_fk     = (const float*)d_in[2];
    const float* lin_w    = (const float*)d_in[3];
    const float* lin_b    = (const float*)d_in[4];
    const float* out_w    = (const float*)d_in[5];
    const float* out_b    = (const float*)d_in[6];
    const float* Wl0      = (const float*)d_in[7];
    const float* Wr0      = (const float*)d_in[8];
    const float* att0     = (const float*)d_in[9];
    const float* b0       = (const float*)d_in[10];
    const float* Wl1      = (const float*)d_in[11];
    const float* Wr1      = (const float*)d_in[12];
    const float* att1     = (const float*)d_in[13];
    const float* b1       = (const float*)d_in[14];
    const int* src_hc = (const int*)d_in[15];
    const int* dst_hc = (const int*)d_in[16];
    const int* src_bt = (const int*)d_in[17];
    const int* dst_bt = (const int*)d_in[18];
    const int* src_is = (const int*)d_in[19];
    const int* dst_is = (const int*)d_in[20];
    const int* src_pt = (const int*)d_in[21];
    const int* dst_pt = (const int*)d_in[22];

    cudaFuncSetAttribute((const void*)gemm_grouped<1, 1, 64, 4, 2>,
                         cudaFuncAttributeMaxDynamicSharedMemorySize, SMEM_BN64);
    cudaFuncSetAttribute((const void*)gemm_grouped<0, 0, 128, 2, 4>,
                         cudaFuncAttributeMaxDynamicSharedMemorySize, SMEM_BN128);

    float* base = nullptr;
    cudaGetSymbolAddress((void**)&base, g_scratch);
    float* feat_t = base + OFF_FEAT_T;
    float* feat_c = base + OFF_FEAT_C;
    float* feat_f = base + OFF_FEAT_F;
    float* xct    = base + OFF_XCT;
    float* xcc    = base + OFF_XCC;
    float* xcf    = base + OFF_XCF;
    float* ot     = base + OFF_OT;
    float* of     = base + OFF_OF;
    float* oc     = base + OFF_OC;
    float* segB   = base + OFF_SEG;
    float* logitB = base + OFF_LOGIT;
    float* rlinT  = base + OFF_RLIN;
    float* routT  = base + OFF_ROUT;
    float* cat0T  = base + OFF_CAT0;
    float* cat1T  = base + OFF_CAT1;
    float* rxt    = base + OFF_RXT;
    float* rxc    = base + OFF_RXC;
    float* rxf    = base + OFF_RXF;

    // 1. prep: weights (round + transpose + concat) and rounded x inputs
    prep_weights<<<(901120 + 255) / 256, 256>>>(lin_w, out_w, Wl0, Wr0, Wl1, Wr1,
                                                rlinT, routT, cat0T, cat1T);
    {
        int tot4 = NT * 64 + NC * 64 + NF * 64;   // 16.64M float4
        round_inputs<<<(tot4 + 255) / 256, 256>>>(x_table, x_column, x_fk, rxt, rxc, rxf);
    }

    const int bT = (NT + 127) / 128;   // 157
    const int bC = (NC + 127) / 128;   // 1563
    const int bF = (NF + 127) / 128;   // 313

    // 2. input projections: one grouped launch (K=256, N=64)
    {
        GemmGroups gp{};
        gp.K = 256;
        gp.A[0] = rxt; gp.B[0] = rlinT;          gp.bias[0] = lin_b;       gp.C[0] = feat_t; gp.M[0] = NT; gp.N[0] = 64;
        gp.A[1] = rxc; gp.B[1] = rlinT + 16384;  gp.bias[1] = lin_b + 64;  gp.C[1] = feat_c; gp.M[1] = NC; gp.N[1] = 64;
        gp.A[2] = rxf; gp.B[2] = rlinT + 32768;  gp.bias[2] = lin_b + 128; gp.C[2] = feat_f; gp.M[2] = NF; gp.N[2] = 64;
        for (int g = 0; g < 3; g++) { gp.maskX[g] = 0; gp.shiftX[g] = 0; }
        gp.blockStart[0] = 0; gp.blockStart[1] = bT; gp.blockStart[2] = bT + bC;
        gemm_grouped<1, 1, 64, 4, 2><<<bT + bC + bF, 256, SMEM_BN64>>>(gp);
    }

    const int* srcs[4] = {src_hc, src_bt, src_is, src_pt};
    const int* dsts[4] = {dst_hc, dst_bt, dst_is, dst_pt};
    const int  Es[4]   = {E_HC, E_BT, E_IS, E_PT};
    const int  nDs[4]  = {NC, NT, NF, NC};
    float* outs[4]     = {oc, ot, of, oc};

    size_t segOffM[4], segOffD[4];
    {
        size_t off = 0;
        for (int c = 0; c < 4; c++) {
            segOffM[c] = off; off += (size_t)nDs[c] * 4;
            segOffD[c] = off; off += (size_t)nDs[c] * 4;
        }
    }
    size_t logOff[4]; { size_t off = 0; for (int c = 0; c < 4; c++) { logOff[c] = off; off += (size_t)Es[c] * 4; } }

    for (int l = 0; l < 2; l++) {
        const int Kin = (l == 0) ? 64 : 256;
        float* catT = (l == 0) ? cat0T : cat1T;
        const float* att = l ? att1 : att0;
        const float* bb  = l ? b1   : b0;

        // 3. concatenated conv projections: one grouped launch
        {
            GemmGroups gp{};
            gp.K = Kin;
            gp.A[0] = feat_t; gp.B[0] = catT;                       gp.bias[0] = nullptr; gp.C[0] = xct; gp.M[0] = NT; gp.N[0] = 512;
            gp.A[1] = feat_c; gp.B[1] = catT + (size_t)512 * Kin;   gp.bias[1] = nullptr; gp.C[1] = xcc; gp.M[1] = NC; gp.N[1] = 1024;
            gp.A[2] = feat_f; gp.B[2] = catT + (size_t)1536 * Kin;  gp.bias[2] = nullptr; gp.C[2] = xcf; gp.M[2] = NF; gp.N[2] = 512;
            gp.maskX[0] = 3; gp.shiftX[0] = 2;
            gp.maskX[1] = 7; gp.shiftX[1] = 3;
            gp.maskX[2] = 3; gp.shiftX[2] = 2;
            gp.blockStart[0] = 0;
            gp.blockStart[1] = bT * 4;
            gp.blockStart[2] = bT * 4 + bC * 8;
            gemm_grouped<0, 0, 128, 2, 4><<<bT * 4 + bC * 8 + bF * 4, 256, SMEM_BN128>>>(gp);
        }

        // 4. zero accumulators (ot|of|oc|seg) with one memset node
        cudaMemsetAsync(ot, 0, ZERO_FLOATS * sizeof(float), 0);

        // 5. batched edge passes
        EdgeB eb{};
        const float* xls[4] = {xct + 0,   xcc + 256, xcc + 512, xcf + 256};
        const int    lss[4] = {512, 1024, 1024, 512};
        const float* xrs[4] = {xcc + 0,   xct + 256, xcf + 0,   xcc + 768};
        const int    rss[4] = {1024, 512, 512, 1024};
        int eacc = 0;
        for (int c = 0; c < 4; c++) {
            eb.src[c] = srcs[c]; eb.dst[c] = dsts[c];
            eb.xl[c] = xls[c]; eb.xr[c] = xrs[c];
            eb.xls[c] = lss[c]; eb.xrs[c] = rss[c];
            eb.logit[c] = logitB + logOff[c];
            eb.segm[c] = (uint32_t*)(segB + segOffM[c]);
            eb.segd[c] = segB + segOffD[c];
            eb.out[c] = outs[c];
            eb.eStart[c] = eacc;
            eacc += Es[c];
        }
        eb.eStart[4] = eacc;
        eb.att = att;

        edge_logits_b<<<(eacc + 7) / 8, 256>>>(eb);
        edge_exp_b<<<(eacc + 255) / 256, 256>>>(eb);
        edge_scatter_b<<<(eacc + 7) / 8, 256>>>(eb);

        // 6. fused ELU / combine with bias fold-in
        int tot4 = NT * 64 + NC * 64 + NF * 64;
        elu_comb<<<(tot4 + 255) / 256, 256>>>(ot, oc, of,
                                              bb + 0, bb + 256, bb + 512, bb + 768,
                                              feat_t, feat_c, feat_f);
    }

    // 7. output heads: one grouped launch
    {
        float* out = (float*)d_out;
        GemmGroups gp{};
        gp.K = 256;
        gp.A[0] = feat_t; gp.B[0] = routT;          gp.bias[0] = out_b;       gp.C[0] = out;                           gp.M[0] = NT; gp.N[0] = 256;
        gp.A[1] = feat_c; gp.B[1] = routT + 65536;  gp.bias[1] = out_b + 256; gp.C[1] = out + (size_t)NT * 256;        gp.M[1] = NC; gp.N[1] = 256;
        gp.A[2] = feat_f; gp.B[2] = routT + 131072; gp.bias[2] = out_b + 512; gp.C[2] = out + (size_t)(NT + NC) * 256; gp.M[2] = NF; gp.N[2] = 256;
        for (int g = 0; g < 3; g++) { gp.maskX[g] = 1; gp.shiftX[g] = 1; }
        gp.blockStart[0] = 0; gp.blockStart[1] = bT * 2; gp.blockStart[2] = bT * 2 + bC * 2;
        gemm_grouped<0, 0, 128, 2, 4><<<(bT + bC + bF) * 2, 256, SMEM_BN128>>>(gp);
    }
}

// round 11
// speedup vs baseline: 1.5195x; 1.5195x over previous
#include <cuda_runtime.h>
#include <math.h>
#include <stdint.h>

// ---------------- problem constants ----------------
#define NT 20000
#define NC 200000
#define NF 40000
#define E_HC 200000
#define E_BT 200000
#define E_IS 80000
#define E_PT 80000
#define FH 256
#define NSLOTS (NC + NT + NF + NC)        // 660000 CSR slots (hc,bt,is,pt)
#define NEDGES (E_HC + E_BT + E_IS + E_PT) // 560000
#define NROWS (NT + NF + NC)              // 260000 gather rows

// ---------------- scratch offsets (floats) ----------------
static constexpr size_t OFF_FEAT_T = 0;
static constexpr size_t OFF_FEAT_C = OFF_FEAT_T + (size_t)NT * 256;
static constexpr size_t OFF_FEAT_F = OFF_FEAT_C + (size_t)NC * 256;
static constexpr size_t OFF_XCT    = OFF_FEAT_F + (size_t)NF * 256;   // NT x 512
static constexpr size_t OFF_XCC    = OFF_XCT + (size_t)NT * 512;      // NC x 1024
static constexpr size_t OFF_XCF    = OFF_XCC + (size_t)NC * 1024;     // NF x 512
static constexpr size_t OFF_OT     = OFF_XCF + (size_t)NF * 512;
static constexpr size_t OFF_OF     = OFF_OT  + (size_t)NT * 256;
static constexpr size_t OFF_OC     = OFF_OF  + (size_t)NF * 256;      // merged hc+pt row
static constexpr size_t OFF_LOGIT  = OFF_OC  + (size_t)NC * 256;      // 560000*4
// CSR int region (counts|cursor adjacent for one memset)
static constexpr size_t OFF_COUNTS = OFF_LOGIT + 2240000;
static constexpr size_t OFF_CURSOR = OFF_COUNTS + NSLOTS;
static constexpr size_t OFF_ROWPTR = OFF_CURSOR + NSLOTS;
static constexpr size_t OFF_BSUM   = OFF_ROWPTR + NSLOTS;
static constexpr size_t OFF_PERM   = OFF_BSUM + 1024;
static constexpr size_t OFF_RLIN   = OFF_PERM + NEDGES;
static constexpr size_t OFF_ROUT   = OFF_RLIN + 49152;
static constexpr size_t OFF_CAT0   = OFF_ROUT + 196608;
static constexpr size_t OFF_CAT1   = OFF_CAT0 + 131072;
static constexpr size_t SCRATCH_TOTAL = OFF_CAT1 + 524288;

__device__ float g_scratch[SCRATCH_TOTAL];

// ---------------- PTX helpers ----------------
__device__ __forceinline__ void cp_async16(void* dst, const void* src)
{
    uint32_t d = (uint32_t)__cvta_generic_to_shared(dst);
    asm volatile("cp.async.cg.shared.global [%0], [%1], 16;\n" :: "r"(d), "l"(src));
}
__device__ __forceinline__ void cp_commit() { asm volatile("cp.async.commit_group;\n" ::: "memory"); }
__device__ __forceinline__ void cp_wait0()  { asm volatile("cp.async.wait_group 0;\n" ::: "memory"); }
__device__ __forceinline__ void cp_wait1()  { asm volatile("cp.async.wait_group 1;\n" ::: "memory"); }

__device__ __forceinline__ uint32_t cvt_tf32(float x)
{
    uint32_t r; asm("cvt.rna.tf32.f32 %0, %1;" : "=r"(r) : "f"(x)); return r;
}
__device__ __forceinline__ float round_tf32(float x) { return __uint_as_float(cvt_tf32(x)); }

__device__ __forceinline__ void mma_tf32(float* c, const uint32_t* a, const uint32_t* b)
{
    asm volatile("mma.sync.aligned.m16n8k8.row.col.f32.tf32.tf32.f32 "
                 "{%0,%1,%2,%3}, {%4,%5,%6,%7}, {%8,%9}, {%0,%1,%2,%3};"
                 : "+f"(c[0]), "+f"(c[1]), "+f"(c[2]), "+f"(c[3])
                 : "r"(a[0]), "r"(a[1]), "r"(a[2]), "r"(a[3]), "r"(b[0]), "r"(b[1]));
}

// ---------------- grouped tf32 GEMM (R8 scalar-LDS version) ----------------
struct GemmGroups {
    const float* A[3]; const float* B[3]; const float* bias[3]; float* C[3];
    int M[3]; int N[3];
    int maskX[3]; int shiftX[3];
    int blockStart[3];
    int K;
};

template<int CVT_A, int ACT, int ROUND_OUT, int BN, int WARPS_M, int WARPS_N>
__global__ void __launch_bounds__(256, 2)
gemm_grouped(GemmGroups gg)
{
    constexpr int BM = 128, BK = 32;
    constexpr int BKP = 36;
    constexpr int BNP = BN + 8;
    constexpr int WM = BM / WARPS_M, WN = BN / WARPS_N;
    constexpr int MI = WM / 16, NI = WN / 8;
    constexpr int A_STAGE = BM * BKP;
    constexpr int B_STAGE = BK * BNP;
    constexpr int STAGES = 3;

    extern __shared__ float sm[];
    float* Asm = sm;
    float* Bsm = sm + STAGES * A_STAGE;

    const int bid = blockIdx.x;
    const int g = (bid >= gg.blockStart[1]) + (bid >= gg.blockStart[2]);
    const int local = bid - gg.blockStart[g];
    const int tileX = local & gg.maskX[g];
    const int tileY = local >> gg.shiftX[g];

    const float* __restrict__ A = gg.A[g];
    const float* __restrict__ B = gg.B[g];
    const float* __restrict__ bias = gg.bias[g];
    float* __restrict__ C = gg.C[g];
    const int M = gg.M[g], N = gg.N[g], K = gg.K;
    const int rowBase = tileY * BM;
    const int colBase = tileX * BN;

    const int tid  = threadIdx.x;
    const int lane = tid & 31;
    const int warp = tid >> 5;
    const int gq   = lane >> 2;
    const int tig  = lane & 3;
    const int warpM = warp % WARPS_M;
    const int warpN = warp / WARPS_M;

    float acc[MI][NI][4];
#pragma unroll
    for (int mi = 0; mi < MI; mi++)
#pragma unroll
        for (int ni = 0; ni < NI; ni++)
#pragma unroll
            for (int q = 0; q < 4; q++) acc[mi][ni][q] = 0.f;

    auto load_tile = [&](int t, int s) {
#pragma unroll
        for (int i = 0; i < 4; i++) {
            int li = tid + i * 256;
            int m = li >> 3;
            int k4 = (li & 7) << 2;
            int gm = rowBase + m;
            if (gm >= M) gm = M - 1;
            cp_async16(Asm + s * A_STAGE + m * BKP + k4,
                       A + (size_t)gm * K + t * BK + k4);
        }
#pragma unroll
        for (int i = 0; i < (BK * BN) / 1024; i++) {
            int li = tid + i * 256;
            int k = li / (BN / 4);
            int n4 = (li % (BN / 4)) << 2;
            cp_async16(Bsm + s * B_STAGE + k * BNP + n4,
                       B + (size_t)(t * BK + k) * N + colBase + n4);
        }
        cp_commit();
    };

    const int nT = K / BK;
    load_tile(0, 0);
    if (nT > 1) load_tile(1, 1);

    for (int t = 0; t < nT; t++) {
        if (t + 1 < nT) cp_wait1(); else cp_wait0();
        __syncthreads();
        if (t + 2 < nT) load_tile(t + 2, (t + 2) % STAGES);

        const float* Asb = Asm + (t % STAGES) * A_STAGE;
        const float* Bsb = Bsm + (t % STAGES) * B_STAGE;
#pragma unroll
        for (int k8 = 0; k8 < BK / 8; k8++) {
            const int kk = k8 * 8;
            uint32_t a[MI][4], b[NI][2];
#pragma unroll
            for (int mi = 0; mi < MI; mi++) {
                const float* ap = Asb + (warpM * WM + mi * 16 + gq) * BKP + kk + tig;
                if (CVT_A) {
                    a[mi][0] = cvt_tf32(ap[0]);
                    a[mi][1] = cvt_tf32(ap[8 * BKP]);
                    a[mi][2] = cvt_tf32(ap[4]);
                    a[mi][3] = cvt_tf32(ap[8 * BKP + 4]);
                } else {
                    a[mi][0] = __float_as_uint(ap[0]);
                    a[mi][1] = __float_as_uint(ap[8 * BKP]);
                    a[mi][2] = __float_as_uint(ap[4]);
                    a[mi][3] = __float_as_uint(ap[8 * BKP + 4]);
                }
            }
#pragma unroll
            for (int ni = 0; ni < NI; ni++) {
                const float* bp = Bsb + (kk + tig) * BNP + warpN * WN + ni * 8 + gq;
                b[ni][0] = __float_as_uint(bp[0]);
                b[ni][1] = __float_as_uint(bp[4 * BNP]);
            }
#pragma unroll
            for (int mi = 0; mi < MI; mi++)
#pragma unroll
                for (int ni = 0; ni < NI; ni++)
                    mma_tf32(acc[mi][ni], a[mi], b[ni]);
        }
    }

#pragma unroll
    for (int mi = 0; mi < MI; mi++) {
        int row0 = rowBase + warpM * WM + mi * 16 + gq;
#pragma unroll
        for (int ni = 0; ni < NI; ni++) {
            int col = colBase + warpN * WN + ni * 8 + tig * 2;
            float bx = 0.f, by = 0.f;
            if (bias) { bx = bias[col]; by = bias[col + 1]; }
            float2 v;
            v.x = acc[mi][ni][0] + bx;
            v.y = acc[mi][ni][1] + by;
            if (ACT == 1) {
                v.x = v.x > 0.f ? v.x : 0.01f * v.x;
                v.y = v.y > 0.f ? v.y : 0.01f * v.y;
            }
            if (ROUND_OUT) { v.x = round_tf32(v.x); v.y = round_tf32(v.y); }
            if (row0 < M) *(float2*)(C + (size_t)row0 * N + col) = v;
            v.x = acc[mi][ni][2] + bx;
            v.y = acc[mi][ni][3] + by;
            if (ACT == 1) {
                v.x = v.x > 0.f ? v.x : 0.01f * v.x;
                v.y = v.y > 0.f ? v.y : 0.01f * v.y;
            }
            if (ROUND_OUT) { v.x = round_tf32(v.x); v.y = round_tf32(v.y); }
            if (row0 + 8 < M) *(float2*)(C + (size_t)(row0 + 8) * N + col) = v;
        }
    }
}

#define SMEM_BN128 (3 * (128*36 + 32*136) * 4)
#define SMEM_BN64  (3 * (128*36 + 32*72)  * 4)

// ---------------- weight prep: round + concat (R8 version) ----------------
__device__ float cat_src(int i, int K, const float* Wl, const float* Wr)
{
    int tN = K * 512, cN = K * 1024;
    if (i < tN) {
        int k = i >> 9, j = i & 511;
        return (j < 256) ? Wl[(0 * K + k) * 256 + j] : Wr[(1 * K + k) * 256 + (j - 256)];
    }
    i -= tN;
    if (i < cN) {
        int k = i >> 10, j = i & 1023;
        int c = j >> 8, col = j & 255;
        const float* p = (c == 0) ? Wr + (0 * K + k) * 256
                       : (c == 1) ? Wl + (1 * K + k) * 256
                       : (c == 2) ? Wl + (2 * K + k) * 256
                                  : Wr + (3 * K + k) * 256;
        return p[col];
    }
    i -= cN;
    int k = i >> 9, j = i & 511;
    return (j < 256) ? Wr[(2 * K + k) * 256 + j] : Wl[(3 * K + k) * 256 + (j - 256)];
}

__global__ void prep_weights(const float* __restrict__ lw, const float* __restrict__ ow,
                             const float* __restrict__ wl0, const float* __restrict__ wr0,
                             const float* __restrict__ wl1, const float* __restrict__ wr1,
                             float* __restrict__ rlin, float* __restrict__ rout,
                             float* __restrict__ cat0, float* __restrict__ cat1)
{
    int i = blockIdx.x * blockDim.x + threadIdx.x;
    if (i < 49152) { rlin[i] = round_tf32(lw[i]); return; }
    i -= 49152;
    if (i < 196608) { rout[i] = round_tf32(ow[i]); return; }
    i -= 196608;
    if (i < 131072) { cat0[i] = round_tf32(cat_src(i, 64, wl0, wr0)); return; }
    i -= 131072;
    if (i < 524288) cat1[i] = round_tf32(cat_src(i, 256, wl1, wr1));
}

// ---------------- CSR build (topology is layer-invariant; built once) -----
struct CsrB {
    const int* dst[4];
    int eStart[5];
    int slotBase[4];
};

__global__ void csr_count(CsrB cb, int* __restrict__ counts)
{
    int i = blockIdx.x * 256 + threadIdx.x;
    if (i >= cb.eStart[4]) return;
    int c = (i >= cb.eStart[2]) ? ((i >= cb.eStart[3]) ? 3 : 2)
                                : ((i >= cb.eStart[1]) ? 1 : 0);
    int e = i - cb.eStart[c];
    atomicAdd(&counts[cb.slotBase[c] + cb.dst[c][e]], 1);
}

__global__ void scan1(const int* __restrict__ cnt, int* __restrict__ incl,
                      int* __restrict__ bsum, int n)
{
    __shared__ int sh[1024];
    int i = blockIdx.x * 1024 + threadIdx.x;
    sh[threadIdx.x] = (i < n) ? cnt[i] : 0;
    __syncthreads();
#pragma unroll
    for (int o = 1; o < 1024; o <<= 1) {
        int t = (threadIdx.x >= o) ? sh[threadIdx.x - o] : 0;
        __syncthreads();
        sh[threadIdx.x] += t;
        __syncthreads();
    }
    if (i < n) incl[i] = sh[threadIdx.x];
    if (threadIdx.x == 1023) bsum[blockIdx.x] = sh[1023];
}

__global__ void scan2(int* __restrict__ bsum, int nb)
{
    __shared__ int sh[1024];
    int t = threadIdx.x;
    sh[t] = (t < nb) ? bsum[t] : 0;
    __syncthreads();
#pragma unroll
    for (int o = 1; o < 1024; o <<= 1) {
        int v = (t >= o) ? sh[t - o] : 0;
        __syncthreads();
        sh[t] += v;
        __syncthreads();
    }
    if (t < nb) bsum[t] = sh[t];
}

__global__ void scan3(const int* __restrict__ cnt, int* __restrict__ ptr,
                      const int* __restrict__ bsum, int n)
{
    int i = blockIdx.x * 1024 + threadIdx.x;
    if (i >= n) return;
    int off = blockIdx.x ? bsum[blockIdx.x - 1] : 0;
    ptr[i] = ptr[i] + off - cnt[i];   // inclusive -> exclusive + block offset
}

__global__ void csr_fill(CsrB cb, const int* __restrict__ rowptr,
                         int* __restrict__ cursor, int* __restrict__ perm)
{
    int i = blockIdx.x * 256 + threadIdx.x;
    if (i >= cb.eStart[4]) return;
    int c = (i >= cb.eStart[2]) ? ((i >= cb.eStart[3]) ? 3 : 2)
                                : ((i >= cb.eStart[1]) ? 1 : 0);
    int e = i - cb.eStart[c];
    int slot = cb.slotBase[c] + cb.dst[c][e];
    int pos = atomicAdd(&cursor[slot], 1);
    perm[rowptr[slot] + pos] = e;
}

// ---------------- edge logits (no segment max needed anymore) ----------------
struct EdgeB {
    const int* src[4]; const int* dst[4];
    const float* xl[4]; const float* xr[4];
    int xls[4], xrs[4];
    const float* att;
    float* logit[4];
    int eStart[5];
};

__global__ void edge_logits_b(EdgeB eb)
{
    int w = blockIdx.x * 8 + (threadIdx.x >> 5);
    if (w >= eb.eStart[4]) return;
    int c = (w >= eb.eStart[2]) ? ((w >= eb.eStart[3]) ? 3 : 2)
                                : ((w >= eb.eStart[1]) ? 1 : 0);
    int e = w - eb.eStart[c];
    int lane = threadIdx.x & 31;
    int s = eb.src[c][e], d = eb.dst[c][e];
    const float4* pl = (const float4*)(eb.xl[c] + (size_t)s * eb.xls[c]) + lane * 2;
    const float4* pr = (const float4*)(eb.xr[c] + (size_t)d * eb.xrs[c]) + lane * 2;
    const float4* pa = (const float4*)(eb.att + c * 256) + lane * 2;
    float sum = 0.f;
#pragma unroll
    for (int i = 0; i < 2; i++) {
        float4 l4 = pl[i], r4 = pr[i], a4 = pa[i];
        float v;
        v = l4.x + r4.x; v = v > 0.f ? v : 0.2f * v; sum += v * a4.x;
        v = l4.y + r4.y; v = v > 0.f ? v : 0.2f * v; sum += v * a4.y;
        v = l4.z + r4.z; v = v > 0.f ? v : 0.2f * v; sum += v * a4.z;
        v = l4.w + r4.w; v = v > 0.f ? v : 0.2f * v; sum += v * a4.w;
    }
    sum += __shfl_xor_sync(0xffffffffu, sum, 1);
    sum += __shfl_xor_sync(0xffffffffu, sum, 2);
    sum += __shfl_xor_sync(0xffffffffu, sum, 4);
    if ((lane & 7) == 0)
        eb.logit[c][(size_t)e * 4 + (lane >> 3)] = sum;
}

// ---------------- per-dst gather: softmax + weighted sum, no atomics -------
struct GatherB {
    const int* srcs[4];
    const float* xl[4]; int xls[4];
    const float* logit[4];
    const int* rowptr; const int* counts; const int* perm;
    int slotBase[4];
};

__device__ __forceinline__ void accum_list(int conv, int slot, const GatherB& g,
                                           float* acc, int lane)
{
    int start = g.rowptr[slot];
    int cnt = g.counts[slot];
    if (cnt == 0) return;
    int h = lane >> 3;
    const float* lg = g.logit[conv];
    const int* sr = g.srcs[conv];
    const float* xl = g.xl[conv];
    int stride = g.xls[conv];

    float m = -1e30f;
    for (int j = 0; j < cnt; j++) {
        int e = g.perm[start + j];
        m = fmaxf(m, lg[(size_t)e * 4 + h]);
    }
    float den = 0.f;
    float num[8];
#pragma unroll
    for (int q = 0; q < 8; q++) num[q] = 0.f;
    for (int j = 0; j < cnt; j++) {
        int e = g.perm[start + j];
        float z = expf(lg[(size_t)e * 4 + h] - m);
        den += z;
        const float4* pl = (const float4*)(xl + (size_t)sr[e] * stride) + lane * 2;
        float4 v0 = pl[0], v1 = pl[1];
        num[0] += z * v0.x; num[1] += z * v0.y; num[2] += z * v0.z; num[3] += z * v0.w;
        num[4] += z * v1.x; num[5] += z * v1.y; num[6] += z * v1.z; num[7] += z * v1.w;
    }
    float inv = 1.f / den;
#pragma unroll
    for (int q = 0; q < 8; q++) acc[q] += num[q] * inv;
}

__global__ void gather_b(GatherB g, float* __restrict__ ot, float* __restrict__ of,
                         float* __restrict__ oc)
{
    int r = blockIdx.x * 8 + (threadIdx.x >> 5);
    if (r >= NROWS) return;
    int lane = threadIdx.x & 31;
    float acc[8];
#pragma unroll
    for (int q = 0; q < 8; q++) acc[q] = 0.f;
    float* out;
    if (r < NT) {                                  // bt -> table rows
        accum_list(1, g.slotBase[1] + r, g, acc, lane);
        out = ot + (size_t)r * 256;
    } else if (r < NT + NF) {                      // is -> fk rows
        int d = r - NT;
        accum_list(2, g.slotBase[2] + d, g, acc, lane);
        out = of + (size_t)d * 256;
    } else {                                       // hc + pt -> column rows
        int d = r - NT - NF;
        accum_list(0, g.slotBase[0] + d, g, acc, lane);
        accum_list(3, g.slotBase[3] + d, g, acc, lane);
        out = oc + (size_t)d * 256;
    }
    float4* po = (float4*)out + lane * 2;
    po[0] = make_float4(acc[0], acc[1], acc[2], acc[3]);
    po[1] = make_float4(acc[4], acc[5], acc[6], acc[7]);
}

// ---------------- fused ELU / combine with bias ----------------
__device__ __forceinline__ float eluf(float x) { return x > 0.f ? x : expm1f(x); }

__global__ void elu_comb(const float* __restrict__ ot, const float* __restrict__ oc,
                         const float* __restrict__ of,
                         const float* __restrict__ b_hc, const float* __restrict__ b_bt,
                         const float* __restrict__ b_is, const float* __restrict__ b_pt,
                         float* __restrict__ ft, float* __restrict__ fc, float* __restrict__ ff)
{
    const int nT4 = NT * 64, nC4 = NC * 64, nF4 = NF * 64;
    int i = blockIdx.x * blockDim.x + threadIdx.x;
    if (i < nT4) {
        float4 v = ((const float4*)ot)[i];
        float4 b = ((const float4*)b_bt)[i & 63];
        v.x = round_tf32(eluf(v.x + b.x)); v.y = round_tf32(eluf(v.y + b.y));
        v.z = round_tf32(eluf(v.z + b.z)); v.w = round_tf32(eluf(v.w + b.w));
        ((float4*)ft)[i] = v;
    } else if (i < nT4 + nC4) {
        int j = i - nT4;
        float4 x = ((const float4*)oc)[j];
        float4 bh = ((const float4*)b_hc)[j & 63];
        float4 bp = ((const float4*)b_pt)[j & 63];
        float4 v;
        v.x = round_tf32(eluf(0.5f * (x.x + bh.x + bp.x)));
        v.y = round_tf32(eluf(0.5f * (x.y + bh.y + bp.y)));
        v.z = round_tf32(eluf(0.5f * (x.z + bh.z + bp.z)));
        v.w = round_tf32(eluf(0.5f * (x.w + bh.w + bp.w)));
        ((float4*)fc)[j] = v;
    } else if (i < nT4 + nC4 + nF4) {
        int j = i - nT4 - nC4;
        float4 v = ((const float4*)of)[j];
        float4 b = ((const float4*)b_is)[j & 63];
        v.x = round_tf32(eluf(v.x + b.x)); v.y = round_tf32(eluf(v.y + b.y));
        v.z = round_tf32(eluf(v.z + b.z)); v.w = round_tf32(eluf(v.w + b.w));
        ((float4*)ff)[j] = v;
    }
}

// ---------------- host orchestration ----------------
extern "C" void kernel_launch(void* const* d_in, const int* in_sizes, int n_in,
                              void* d_out, int out_size)
{
    (void)in_sizes; (void)n_in; (void)out_size;
    const float* x_table  = (const float*)d_in[0];
    const float* x_column = (const float*)d_in[1];
    const float* x_fk     = (const float*)d_in[2];
    const float* lin_w    = (const float*)d_in[3];
    const float* lin_b    = (const float*)d_in[4];
    const float* out_w    = (const float*)d_in[5];
    const float* out_b    = (const float*)d_in[6];
    const float* Wl0      = (const float*)d_in[7];
    const float* Wr0      = (const float*)d_in[8];
    const float* att0     = (const float*)d_in[9];
    const float* b0       = (const float*)d_in[10];
    const float* Wl1      = (const float*)d_in[11];
    const float* Wr1      = (const float*)d_in[12];
    const float* att1     = (const float*)d_in[13];
    const float* b1       = (const float*)d_in[14];
    const int* src_hc = (const int*)d_in[15];
    const int* dst_hc = (const int*)d_in[16];
    const int* src_bt = (const int*)d_in[17];
    const int* dst_bt = (const int*)d_in[18];
    const int* src_is = (const int*)d_in[19];
    const int* dst_is = (const int*)d_in[20];
    const int* src_pt = (const int*)d_in[21];
    const int* dst_pt = (const int*)d_in[22];

    cudaFuncSetAttribute((const void*)gemm_grouped<1, 1, 1, 64, 4, 2>,
                         cudaFuncAttributeMaxDynamicSharedMemorySize, SMEM_BN64);
    cudaFuncSetAttribute((const void*)gemm_grouped<0, 0, 0, 128, 2, 4>,
                         cudaFuncAttributeMaxDynamicSharedMemorySize, SMEM_BN128);

    float* base = nullptr;
    cudaGetSymbolAddress((void**)&base, g_scratch);
    float* feat_t = base + OFF_FEAT_T;
    float* feat_c = base + OFF_FEAT_C;
    float* feat_f = base + OFF_FEAT_F;
    float* xct    = base + OFF_XCT;
    float* xcc    = base + OFF_XCC;
    float* xcf    = base + OFF_XCF;
    float* ot     = base + OFF_OT;
    float* of     = base + OFF_OF;
    float* oc     = base + OFF_OC;
    float* logitB = base + OFF_LOGIT;
    int* counts   = (int*)(base + OFF_COUNTS);
    int* cursor   = (int*)(base + OFF_CURSOR);
    int* rowptr   = (int*)(base + OFF_ROWPTR);
    int* bsum     = (int*)(base + OFF_BSUM);
    int* perm     = (int*)(base + OFF_PERM);
    float* rlin   = base + OFF_RLIN;
    float* rout   = base + OFF_ROUT;
    float* cat0   = base + OFF_CAT0;
    float* cat1   = base + OFF_CAT1;

    // 1. weight prep
    prep_weights<<<(901120 + 255) / 256, 256>>>(lin_w, out_w, Wl0, Wr0, Wl1, Wr1,
                                                rlin, rout, cat0, cat1);

    // 2. CSR build (once; topology layer-invariant)
    const int slotBase[4] = {0, NC, NC + NT, NC + NT + NF};
    CsrB cb{};
    cb.dst[0] = dst_hc; cb.dst[1] = dst_bt; cb.dst[2] = dst_is; cb.dst[3] = dst_pt;
    cb.eStart[0] = 0; cb.eStart[1] = E_HC; cb.eStart[2] = E_HC + E_BT;
    cb.eStart[3] = E_HC + E_BT + E_IS; cb.eStart[4] = NEDGES;
    for (int c = 0; c < 4; c++) cb.slotBase[c] = slotBase[c];

    cudaMemsetAsync(counts, 0, (size_t)NSLOTS * 2 * sizeof(int), 0);  // counts + cursor
    csr_count<<<(NEDGES + 255) / 256, 256>>>(cb, counts);
    const int nScanBlocks = (NSLOTS + 1023) / 1024;   // 645
    scan1<<<nScanBlocks, 1024>>>(counts, rowptr, bsum, NSLOTS);
    scan2<<<1, 1024>>>(bsum, nScanBlocks);
    scan3<<<nScanBlocks, 1024>>>(counts, rowptr, bsum, NSLOTS);
    csr_fill<<<(NEDGES + 255) / 256, 256>>>(cb, rowptr, cursor, perm);

    const int bT = (NT + 127) / 128;   // 157
    const int bC = (NC + 127) / 128;   // 1563
    const int bF = (NF + 127) / 128;   // 313

    // 3. input projections: one grouped launch
    {
        GemmGroups gp{};
        gp.K = 256;
        gp.A[0] = x_table;  gp.B[0] = rlin;          gp.bias[0] = lin_b;       gp.C[0] = feat_t; gp.M[0] = NT; gp.N[0] = 64;
        gp.A[1] = x_column; gp.B[1] = rlin + 16384;  gp.bias[1] = lin_b + 64;  gp.C[1] = feat_c; gp.M[1] = NC; gp.N[1] = 64;
        gp.A[2] = x_fk;     gp.B[2] = rlin + 32768;  gp.bias[2] = lin_b + 128; gp.C[2] = feat_f; gp.M[2] = NF; gp.N[2] = 64;
        for (int g = 0; g < 3; g++) { gp.maskX[g] = 0; gp.shiftX[g] = 0; }
        gp.blockStart[0] = 0; gp.blockStart[1] = bT; gp.blockStart[2] = bT + bC;
        gemm_grouped<1, 1, 1, 64, 4, 2><<<bT + bC + bF, 256, SMEM_BN64>>>(gp);
    }

    const int* srcs[4] = {src_hc, src_bt, src_is, src_pt};
    const int* dsts[4] = {dst_hc, dst_bt, dst_is, dst_pt};
    const int  Es[4]   = {E_HC, E_BT, E_IS, E_PT};
    size_t logOff[4];
    { size_t off = 0; for (int c = 0; c < 4; c++) { logOff[c] = off; off += (size_t)Es[c] * 4; } }

    const float* xls[4] = {xct + 0,   xcc + 256, xcc + 512, xcf + 256};
    const int    lss[4] = {512, 1024, 1024, 512};
    const float* xrs[4] = {xcc + 0,   xct + 256, xcf + 0,   xcc + 768};
    const int    rss[4] = {1024, 512, 512, 1024};

    for (int l = 0; l < 2; l++) {
        const int Kin = (l == 0) ? 64 : 256;
        float* cat = (l == 0) ? cat0 : cat1;
        const float* att = l ? att1 : att0;
        const float* bb  = l ? b1   : b0;

        // 4. concatenated conv projections: one grouped launch
        {
            GemmGroups gp{};
            gp.K = Kin;
            gp.A[0] = feat_t; gp.B[0] = cat;                      gp.bias[0] = nullptr; gp.C[0] = xct; gp.M[0] = NT; gp.N[0] = 512;
            gp.A[1] = feat_c; gp.B[1] = cat + (size_t)Kin * 512;  gp.bias[1] = nullptr; gp.C[1] = xcc; gp.M[1] = NC; gp.N[1] = 1024;
            gp.A[2] = feat_f; gp.B[2] = cat + (size_t)Kin * 1536; gp.bias[2] = nullptr; gp.C[2] = xcf; gp.M[2] = NF; gp.N[2] = 512;
            gp.maskX[0] = 3; gp.shiftX[0] = 2;
            gp.maskX[1] = 7; gp.shiftX[1] = 3;
            gp.maskX[2] = 3; gp.shiftX[2] = 2;
            gp.blockStart[0] = 0;
            gp.blockStart[1] = bT * 4;
            gp.blockStart[2] = bT * 4 + bC * 8;
            gemm_grouped<0, 0, 0, 128, 2, 4><<<bT * 4 + bC * 8 + bF * 4, 256, SMEM_BN128>>>(gp);
        }

        // 5. edge logits
        EdgeB eb{};
        for (int c = 0; c < 4; c++) {
            eb.src[c] = srcs[c]; eb.dst[c] = dsts[c];
            eb.xl[c] = xls[c]; eb.xr[c] = xrs[c];
            eb.xls[c] = lss[c]; eb.xrs[c] = rss[c];
            eb.logit[c] = logitB + logOff[c];
            eb.eStart[c] = cb.eStart[c];
        }
        eb.eStart[4] = NEDGES;
        eb.att = att;
        edge_logits_b<<<(NEDGES + 7) / 8, 256>>>(eb);

        // 6. per-dst gather (softmax + weighted sum, writes rows directly)
        GatherB g{};
        for (int c = 0; c < 4; c++) {
            g.srcs[c] = srcs[c];
            g.xl[c] = xls[c]; g.xls[c] = lss[c];
            g.logit[c] = logitB + logOff[c];
            g.slotBase[c] = slotBase[c];
        }
        g.rowptr = rowptr; g.counts = counts; g.perm = perm;
        gather_b<<<(NROWS + 7) / 8, 256>>>(g, ot, of, oc);

        // 7. fused ELU / combine with bias fold-in
        int tot4 = NT * 64 + NC * 64 + NF * 64;
        elu_comb<<<(tot4 + 255) / 256, 256>>>(ot, oc, of,
                                              bb + 0, bb + 256, bb + 512, bb + 768,
                                              feat_t, feat_c, feat_f);
    }

    // 8. output heads: one grouped launch
    {
        float* out = (float*)d_out;
        GemmGroups gp{};
        gp.K = 256;
        gp.A[0] = feat_t; gp.B[0] = rout;          gp.bias[0] = out_b;       gp.C[0] = out;                           gp.M[0] = NT; gp.N[0] = 256;
        gp.A[1] = feat_c; gp.B[1] = rout + 65536;  gp.bias[1] = out_b + 256; gp.C[1] = out + (size_t)NT * 256;        gp.M[1] = NC; gp.N[1] = 256;
        gp.A[2] = feat_f; gp.B[2] = rout + 131072; gp.bias[2] = out_b + 512; gp.C[2] = out + (size_t)(NT + NC) * 256; gp.M[2] = NF; gp.N[2] = 256;
        for (int g = 0; g < 3; g++) { gp.maskX[g] = 1; gp.shiftX[g] = 1; }
        gp.blockStart[0] = 0; gp.blockStart[1] = bT * 2; gp.blockStart[2] = bT * 2 + bC * 2;
        gemm_grouped<0, 0, 0, 128, 2, 4><<<(bT + bC + bF) * 2, 256, SMEM_BN128>>>(gp);
    }
}

// round 13
// speedup vs baseline: 1.6108x; 1.0601x over previous
#include <cuda_runtime.h>
#include <math.h>
#include <stdint.h>

// ---------------- problem constants ----------------
#define NT 20000
#define NC 200000
#define NF 40000
#define E_HC 200000
#define E_BT 200000
#define E_IS 80000
#define E_PT 80000
#define FH 256
#define NSLOTS (NC + NT + NF + NC)         // 660000 CSR slots (hc,bt,is,pt)
#define NEDGES (E_HC + E_BT + E_IS + E_PT) // 560000
#define NROWS (NT + NF + NC)               // 260000 gather rows

// ---------------- scratch offsets (floats) ----------------
static constexpr size_t OFF_FEAT_T = 0;
static constexpr size_t OFF_FEAT_C = OFF_FEAT_T + (size_t)NT * 256;
static constexpr size_t OFF_FEAT_F = OFF_FEAT_C + (size_t)NC * 256;
static constexpr size_t OFF_XCT    = OFF_FEAT_F + (size_t)NF * 256;   // NT x 512
static constexpr size_t OFF_XCC    = OFF_XCT + (size_t)NT * 512;      // NC x 1024
static constexpr size_t OFF_XCF    = OFF_XCC + (size_t)NC * 1024;     // NF x 512
static constexpr size_t OFF_OT     = OFF_XCF + (size_t)NF * 512;
static constexpr size_t OFF_OF     = OFF_OT  + (size_t)NT * 256;
static constexpr size_t OFF_OC     = OFF_OF  + (size_t)NF * 256;      // merged hc+pt row
// CSR int region (counts|cursor adjacent for one memset)
static constexpr size_t OFF_COUNTS = OFF_OC + (size_t)NC * 256;
static constexpr size_t OFF_CURSOR = OFF_COUNTS + NSLOTS;
static constexpr size_t OFF_ROWPTR = OFF_CURSOR + NSLOTS;
static constexpr size_t OFF_BSUM   = OFF_ROWPTR + NSLOTS;
static constexpr size_t OFF_PERM   = OFF_BSUM + 1024;
static constexpr size_t OFF_RLIN   = OFF_PERM + NEDGES;
static constexpr size_t OFF_ROUT   = OFF_RLIN + 49152;
static constexpr size_t OFF_CAT0   = OFF_ROUT + 196608;
static constexpr size_t OFF_CAT1   = OFF_CAT0 + 131072;
static constexpr size_t SCRATCH_TOTAL = OFF_CAT1 + 524288;

__device__ float g_scratch[SCRATCH_TOTAL];

// ---------------- PTX helpers ----------------
__device__ __forceinline__ void cp_async16(void* dst, const void* src)
{
    uint32_t d = (uint32_t)__cvta_generic_to_shared(dst);
    asm volatile("cp.async.cg.shared.global [%0], [%1], 16;\n" :: "r"(d), "l"(src));
}
__device__ __forceinline__ void cp_commit() { asm volatile("cp.async.commit_group;\n" ::: "memory"); }
__device__ __forceinline__ void cp_wait0()  { asm volatile("cp.async.wait_group 0;\n" ::: "memory"); }
__device__ __forceinline__ void cp_wait1()  { asm volatile("cp.async.wait_group 1;\n" ::: "memory"); }

__device__ __forceinline__ uint32_t cvt_tf32(float x)
{
    uint32_t r; asm("cvt.rna.tf32.f32 %0, %1;" : "=r"(r) : "f"(x)); return r;
}
__device__ __forceinline__ float round_tf32(float x) { return __uint_as_float(cvt_tf32(x)); }

__device__ __forceinline__ void mma_tf32(float* c, const uint32_t* a, const uint32_t* b)
{
    asm volatile("mma.sync.aligned.m16n8k8.row.col.f32.tf32.tf32.f32 "
                 "{%0,%1,%2,%3}, {%4,%5,%6,%7}, {%8,%9}, {%0,%1,%2,%3};"
                 : "+f"(c[0]), "+f"(c[1]), "+f"(c[2]), "+f"(c[3])
                 : "r"(a[0]), "r"(a[1]), "r"(a[2]), "r"(a[3]), "r"(b[0]), "r"(b[1]));
}

// ---------------- grouped tf32 GEMM (proven R8/R11 version) ----------------
struct GemmGroups {
    const float* A[3]; const float* B[3]; const float* bias[3]; float* C[3];
    int M[3]; int N[3];
    int maskX[3]; int shiftX[3];
    int blockStart[3];
    int K;
};

template<int CVT_A, int ACT, int ROUND_OUT, int BN, int WARPS_M, int WARPS_N>
__global__ void __launch_bounds__(256, 2)
gemm_grouped(GemmGroups gg)
{
    constexpr int BM = 128, BK = 32;
    constexpr int BKP = 36;
    constexpr int BNP = BN + 8;
    constexpr int WM = BM / WARPS_M, WN = BN / WARPS_N;
    constexpr int MI = WM / 16, NI = WN / 8;
    constexpr int A_STAGE = BM * BKP;
    constexpr int B_STAGE = BK * BNP;
    constexpr int STAGES = 3;

    extern __shared__ float sm[];
    float* Asm = sm;
    float* Bsm = sm + STAGES * A_STAGE;

    const int bid = blockIdx.x;
    const int g = (bid >= gg.blockStart[1]) + (bid >= gg.blockStart[2]);
    const int local = bid - gg.blockStart[g];
    const int tileX = local & gg.maskX[g];
    const int tileY = local >> gg.shiftX[g];

    const float* __restrict__ A = gg.A[g];
    const float* __restrict__ B = gg.B[g];
    const float* __restrict__ bias = gg.bias[g];
    float* __restrict__ C = gg.C[g];
    const int M = gg.M[g], N = gg.N[g], K = gg.K;
    const int rowBase = tileY * BM;
    const int colBase = tileX * BN;

    const int tid  = threadIdx.x;
    const int lane = tid & 31;
    const int warp = tid >> 5;
    const int gq   = lane >> 2;
    const int tig  = lane & 3;
    const int warpM = warp % WARPS_M;
    const int warpN = warp / WARPS_M;

    float acc[MI][NI][4];
#pragma unroll
    for (int mi = 0; mi < MI; mi++)
#pragma unroll
        for (int ni = 0; ni < NI; ni++)
#pragma unroll
            for (int q = 0; q < 4; q++) acc[mi][ni][q] = 0.f;

    auto load_tile = [&](int t, int s) {
#pragma unroll
        for (int i = 0; i < 4; i++) {
            int li = tid + i * 256;
            int m = li >> 3;
            int k4 = (li & 7) << 2;
            int gm = rowBase + m;
            if (gm >= M) gm = M - 1;
            cp_async16(Asm + s * A_STAGE + m * BKP + k4,
                       A + (size_t)gm * K + t * BK + k4);
        }
#pragma unroll
        for (int i = 0; i < (BK * BN) / 1024; i++) {
            int li = tid + i * 256;
            int k = li / (BN / 4);
            int n4 = (li % (BN / 4)) << 2;
            cp_async16(Bsm + s * B_STAGE + k * BNP + n4,
                       B + (size_t)(t * BK + k) * N + colBase + n4);
        }
        cp_commit();
    };

    const int nT = K / BK;
    load_tile(0, 0);
    if (nT > 1) load_tile(1, 1);

    for (int t = 0; t < nT; t++) {
        if (t + 1 < nT) cp_wait1(); else cp_wait0();
        __syncthreads();
        if (t + 2 < nT) load_tile(t + 2, (t + 2) % STAGES);

        const float* Asb = Asm + (t % STAGES) * A_STAGE;
        const float* Bsb = Bsm + (t % STAGES) * B_STAGE;
#pragma unroll
        for (int k8 = 0; k8 < BK / 8; k8++) {
            const int kk = k8 * 8;
            uint32_t a[MI][4], b[NI][2];
#pragma unroll
            for (int mi = 0; mi < MI; mi++) {
                const float* ap = Asb + (warpM * WM + mi * 16 + gq) * BKP + kk + tig;
                if (CVT_A) {
                    a[mi][0] = cvt_tf32(ap[0]);
                    a[mi][1] = cvt_tf32(ap[8 * BKP]);
                    a[mi][2] = cvt_tf32(ap[4]);
                    a[mi][3] = cvt_tf32(ap[8 * BKP + 4]);
                } else {
                    a[mi][0] = __float_as_uint(ap[0]);
                    a[mi][1] = __float_as_uint(ap[8 * BKP]);
                    a[mi][2] = __float_as_uint(ap[4]);
                    a[mi][3] = __float_as_uint(ap[8 * BKP + 4]);
                }
            }
#pragma unroll
            for (int ni = 0; ni < NI; ni++) {
                const float* bp = Bsb + (kk + tig) * BNP + warpN * WN + ni * 8 + gq;
                b[ni][0] = __float_as_uint(bp[0]);
                b[ni][1] = __float_as_uint(bp[4 * BNP]);
            }
#pragma unroll
            for (int mi = 0; mi < MI; mi++)
#pragma unroll
                for (int ni = 0; ni < NI; ni++)
                    mma_tf32(acc[mi][ni], a[mi], b[ni]);
        }
    }

#pragma unroll
    for (int mi = 0; mi < MI; mi++) {
        int row0 = rowBase + warpM * WM + mi * 16 + gq;
#pragma unroll
        for (int ni = 0; ni < NI; ni++) {
            int col = colBase + warpN * WN + ni * 8 + tig * 2;
            float bx = 0.f, by = 0.f;
            if (bias) { bx = bias[col]; by = bias[col + 1]; }
            float2 v;
            v.x = acc[mi][ni][0] + bx;
            v.y = acc[mi][ni][1] + by;
            if (ACT == 1) {
                v.x = v.x > 0.f ? v.x : 0.01f * v.x;
                v.y = v.y > 0.f ? v.y : 0.01f * v.y;
            }
            if (ROUND_OUT) { v.x = round_tf32(v.x); v.y = round_tf32(v.y); }
            if (row0 < M) *(float2*)(C + (size_t)row0 * N + col) = v;
            v.x = acc[mi][ni][2] + bx;
            v.y = acc[mi][ni][3] + by;
            if (ACT == 1) {
                v.x = v.x > 0.f ? v.x : 0.01f * v.x;
                v.y = v.y > 0.f ? v.y : 0.01f * v.y;
            }
            if (ROUND_OUT) { v.x = round_tf32(v.x); v.y = round_tf32(v.y); }
            if (row0 + 8 < M) *(float2*)(C + (size_t)(row0 + 8) * N + col) = v;
        }
    }
}

#define SMEM_BN128 (3 * (128*36 + 32*136) * 4)
#define SMEM_BN64  (3 * (128*36 + 32*72)  * 4)

// ---------------- weight prep: round + concat ----------------
__device__ float cat_src(int i, int K, const float* Wl, const float* Wr)
{
    int tN = K * 512, cN = K * 1024;
    if (i < tN) {
        int k = i >> 9, j = i & 511;
        return (j < 256) ? Wl[(0 * K + k) * 256 + j] : Wr[(1 * K + k) * 256 + (j - 256)];
    }
    i -= tN;
    if (i < cN) {
        int k = i >> 10, j = i & 1023;
        int c = j >> 8, col = j & 255;
        const float* p = (c == 0) ? Wr + (0 * K + k) * 256
                       : (c == 1) ? Wl + (1 * K + k) * 256
                       : (c == 2) ? Wl + (2 * K + k) * 256
                                  : Wr + (3 * K + k) * 256;
        return p[col];
    }
    i -= cN;
    int k = i >> 9, j = i & 511;
    return (j < 256) ? Wr[(2 * K + k) * 256 + j] : Wl[(3 * K + k) * 256 + (j - 256)];
}

__global__ void prep_weights(const float* __restrict__ lw, const float* __restrict__ ow,
                             const float* __restrict__ wl0, const float* __restrict__ wr0,
                             const float* __restrict__ wl1, const float* __restrict__ wr1,
                             float* __restrict__ rlin, float* __restrict__ rout,
                             float* __restrict__ cat0, float* __restrict__ cat1)
{
    int i = blockIdx.x * blockDim.x + threadIdx.x;
    if (i < 49152) { rlin[i] = round_tf32(lw[i]); return; }
    i -= 49152;
    if (i < 196608) { rout[i] = round_tf32(ow[i]); return; }
    i -= 196608;
    if (i < 131072) { cat0[i] = round_tf32(cat_src(i, 64, wl0, wr0)); return; }
    i -= 131072;
    if (i < 524288) cat1[i] = round_tf32(cat_src(i, 256, wl1, wr1));
}

// ---------------- CSR build (topology layer-invariant; built once) -----
struct CsrB {
    const int* dst[4];
    int eStart[5];
    int slotBase[4];
};

__global__ void csr_count(CsrB cb, int* __restrict__ counts)
{
    int i = blockIdx.x * 256 + threadIdx.x;
    if (i >= cb.eStart[4]) return;
    int c = (i >= cb.eStart[2]) ? ((i >= cb.eStart[3]) ? 3 : 2)
                                : ((i >= cb.eStart[1]) ? 1 : 0);
    int e = i - cb.eStart[c];
    atomicAdd(&counts[cb.slotBase[c] + cb.dst[c][e]], 1);
}

__global__ void scan1(const int* __restrict__ cnt, int* __restrict__ incl,
                      int* __restrict__ bsum, int n)
{
    __shared__ int sh[1024];
    int i = blockIdx.x * 1024 + threadIdx.x;
    sh[threadIdx.x] = (i < n) ? cnt[i] : 0;
    __syncthreads();
#pragma unroll
    for (int o = 1; o < 1024; o <<= 1) {
        int t = (threadIdx.x >= o) ? sh[threadIdx.x - o] : 0;
        __syncthreads();
        sh[threadIdx.x] += t;
        __syncthreads();
    }
    if (i < n) incl[i] = sh[threadIdx.x];
    if (threadIdx.x == 1023) bsum[blockIdx.x] = sh[1023];
}

__global__ void scan2(int* __restrict__ bsum, int nb)
{
    __shared__ int sh[1024];
    int t = threadIdx.x;
    sh[t] = (t < nb) ? bsum[t] : 0;
    __syncthreads();
#pragma unroll
    for (int o = 1; o < 1024; o <<= 1) {
        int v = (t >= o) ? sh[t - o] : 0;
        __syncthreads();
        sh[t] += v;
        __syncthreads();
    }
    if (t < nb) bsum[t] = sh[t];
}

__global__ void scan3(const int* __restrict__ cnt, int* __restrict__ ptr,
                      const int* __restrict__ bsum, int n)
{
    int i = blockIdx.x * 1024 + threadIdx.x;
    if (i >= n) return;
    int off = blockIdx.x ? bsum[blockIdx.x - 1] : 0;
    ptr[i] = ptr[i] + off - cnt[i];   // inclusive -> exclusive + block offset
}

__global__ void csr_fill(CsrB cb, const int* __restrict__ rowptr,
                         int* __restrict__ cursor, int* __restrict__ perm)
{
    int i = blockIdx.x * 256 + threadIdx.x;
    if (i >= cb.eStart[4]) return;
    int c = (i >= cb.eStart[2]) ? ((i >= cb.eStart[3]) ? 3 : 2)
                                : ((i >= cb.eStart[1]) ? 1 : 0);
    int e = i - cb.eStart[c];
    int slot = cb.slotBase[c] + cb.dst[c][e];
    int pos = atomicAdd(&cursor[slot], 1);
    perm[rowptr[slot] + pos] = e;
}

// ---------------- fused gather: logits + softmax + weighted sum -----------
// One warp per dst row. Per edge: load xl[src] row once, compute the GATv2
// logit inline against the register-cached xr[dst] row + att, accumulate
// z = exp(logit) (logits are O(1): no max shift needed) and z * xl.
struct GatherB {
    const int* srcs[4];
    const float* xl[4]; int xls[4];
    const float* xr[4]; int xrs[4];
    const float* att;                 // conv c at att + c*256
    const int* rowptr; const int* counts; const int* perm;
    int slotBase[4];
};

__device__ __forceinline__ void accum_fused(int conv, int slot, int d,
                                            const GatherB& g, float* acc, int lane)
{
    int cnt = g.counts[slot];
    if (cnt == 0) return;
    int start = g.rowptr[slot];

    const float4* pr = (const float4*)(g.xr[conv] + (size_t)d * g.xrs[conv]) + lane * 2;
    float4 r0 = pr[0], r1 = pr[1];
    const float4* pa = (const float4*)(g.att + conv * 256) + lane * 2;
    float4 a0 = pa[0], a1 = pa[1];

    const int* sr = g.srcs[conv];
    const float* xlp = g.xl[conv];
    int stride = g.xls[conv];

    float den = 0.f;
    float num[8];
#pragma unroll
    for (int q = 0; q < 8; q++) num[q] = 0.f;

    for (int j = 0; j < cnt; j++) {
        int e = g.perm[start + j];
        const float4* pl = (const float4*)(xlp + (size_t)sr[e] * stride) + lane * 2;
        float4 l0 = pl[0], l1 = pl[1];
        float t = 0.f, v;
        v = l0.x + r0.x; v = v > 0.f ? v : 0.2f * v; t += v * a0.x;
        v = l0.y + r0.y; v = v > 0.f ? v : 0.2f * v; t += v * a0.y;
        v = l0.z + r0.z; v = v > 0.f ? v : 0.2f * v; t += v * a0.z;
        v = l0.w + r0.w; v = v > 0.f ? v : 0.2f * v; t += v * a0.w;
        v = l1.x + r1.x; v = v > 0.f ? v : 0.2f * v; t += v * a1.x;
        v = l1.y + r1.y; v = v > 0.f ? v : 0.2f * v; t += v * a1.y;
        v = l1.z + r1.z; v = v > 0.f ? v : 0.2f * v; t += v * a1.z;
        v = l1.w + r1.w; v = v > 0.f ? v : 0.2f * v; t += v * a1.w;
        t += __shfl_xor_sync(0xffffffffu, t, 1);
        t += __shfl_xor_sync(0xffffffffu, t, 2);
        t += __shfl_xor_sync(0xffffffffu, t, 4);   // full head logit in all 8 lanes
        float z = expf(t);
        den += z;
        num[0] += z * l0.x; num[1] += z * l0.y; num[2] += z * l0.z; num[3] += z * l0.w;
        num[4] += z * l1.x; num[5] += z * l1.y; num[6] += z * l1.z; num[7] += z * l1.w;
    }
    float inv = 1.f / den;
#pragma unroll
    for (int q = 0; q < 8; q++) acc[q] += num[q] * inv;
}

__global__ void gather_b(GatherB g, float* __restrict__ ot, float* __restrict__ of,
                         float* __restrict__ oc)
{
    int r = blockIdx.x * 8 + (threadIdx.x >> 5);
    if (r >= NROWS) return;
    int lane = threadIdx.x & 31;
    float acc[8];
#pragma unroll
    for (int q = 0; q < 8; q++) acc[q] = 0.f;
    float* out;
    if (r < NT) {                                  // bt -> table rows
        accum_fused(1, g.slotBase[1] + r, r, g, acc, lane);
        out = ot + (size_t)r * 256;
    } else if (r < NT + NF) {                      // is -> fk rows
        int d = r - NT;
        accum_fused(2, g.slotBase[2] + d, d, g, acc, lane);
        out = of + (size_t)d * 256;
    } else {                                       // hc + pt -> column rows
        int d = r - NT - NF;
        accum_fused(0, g.slotBase[0] + d, d, g, acc, lane);
        accum_fused(3, g.slotBase[3] + d, d, g, acc, lane);
        out = oc + (size_t)d * 256;
    }
    float4* po = (float4*)out + lane * 2;
    po[0] = make_float4(acc[0], acc[1], acc[2], acc[3]);
    po[1] = make_float4(acc[4], acc[5], acc[6], acc[7]);
}

// ---------------- fused ELU / combine with bias ----------------
__device__ __forceinline__ float eluf(float x) { return x > 0.f ? x : expm1f(x); }

__global__ void elu_comb(const float* __restrict__ ot, const float* __restrict__ oc,
                         const float* __restrict__ of,
                         const float* __restrict__ b_hc, const float* __restrict__ b_bt,
                         const float* __restrict__ b_is, const float* __restrict__ b_pt,
                         float* __restrict__ ft, float* __restrict__ fc, float* __restrict__ ff)
{
    const int nT4 = NT * 64, nC4 = NC * 64, nF4 = NF * 64;
    int i = blockIdx.x * blockDim.x + threadIdx.x;
    if (i < nT4) {
        float4 v = ((const float4*)ot)[i];
        float4 b = ((const float4*)b_bt)[i & 63];
        v.x = round_tf32(eluf(v.x + b.x)); v.y = round_tf32(eluf(v.y + b.y));
        v.z = round_tf32(eluf(v.z + b.z)); v.w = round_tf32(eluf(v.w + b.w));
        ((float4*)ft)[i] = v;
    } else if (i < nT4 + nC4) {
        int j = i - nT4;
        float4 x = ((const float4*)oc)[j];
        float4 bh = ((const float4*)b_hc)[j & 63];
        float4 bp = ((const float4*)b_pt)[j & 63];
        float4 v;
        v.x = round_tf32(eluf(0.5f * (x.x + bh.x + bp.x)));
        v.y = round_tf32(eluf(0.5f * (x.y + bh.y + bp.y)));
        v.z = round_tf32(eluf(0.5f * (x.z + bh.z + bp.z)));
        v.w = round_tf32(eluf(0.5f * (x.w + bh.w + bp.w)));
        ((float4*)fc)[j] = v;
    } else if (i < nT4 + nC4 + nF4) {
        int j = i - nT4 - nC4;
        float4 v = ((const float4*)of)[j];
        float4 b = ((const float4*)b_is)[j & 63];
        v.x = round_tf32(eluf(v.x + b.x)); v.y = round_tf32(eluf(v.y + b.y));
        v.z = round_tf32(eluf(v.z + b.z)); v.w = round_tf32(eluf(v.w + b.w));
        ((float4*)ff)[j] = v;
    }
}

// ---------------- host orchestration ----------------
extern "C" void kernel_launch(void* const* d_in, const int* in_sizes, int n_in,
                              void* d_out, int out_size)
{
    (void)in_sizes; (void)n_in; (void)out_size;
    const float* x_table  = (const float*)d_in[0];
    const float* x_column = (const float*)d_in[1];
    const float* x_fk     = (const float*)d_in[2];
    const float* lin_w    = (const float*)d_in[3];
    const float* lin_b    = (const float*)d_in[4];
    const float* out_w    = (const float*)d_in[5];
    const float* out_b    = (const float*)d_in[6];
    const float* Wl0      = (const float*)d_in[7];
    const float* Wr0      = (const float*)d_in[8];
    const float* att0     = (const float*)d_in[9];
    const float* b0       = (const float*)d_in[10];
    const float* Wl1      = (const float*)d_in[11];
    const float* Wr1      = (const float*)d_in[12];
    const float* att1     = (const float*)d_in[13];
    const float* b1       = (const float*)d_in[14];
    const int* src_hc = (const int*)d_in[15];
    const int* dst_hc = (const int*)d_in[16];
    const int* src_bt = (const int*)d_in[17];
    const int* dst_bt = (const int*)d_in[18];
    const int* src_is = (const int*)d_in[19];
    const int* dst_is = (const int*)d_in[20];
    const int* src_pt = (const int*)d_in[21];
    const int* dst_pt = (const int*)d_in[22];

    cudaFuncSetAttribute((const void*)gemm_grouped<1, 1, 1, 64, 4, 2>,
                         cudaFuncAttributeMaxDynamicSharedMemorySize, SMEM_BN64);
    cudaFuncSetAttribute((const void*)gemm_grouped<0, 0, 0, 128, 2, 4>,
                         cudaFuncAttributeMaxDynamicSharedMemorySize, SMEM_BN128);

    float* base = nullptr;
    cudaGetSymbolAddress((void**)&base, g_scratch);
    float* feat_t = base + OFF_FEAT_T;
    float* feat_c = base + OFF_FEAT_C;
    float* feat_f = base + OFF_FEAT_F;
    float* xct    = base + OFF_XCT;
    float* xcc    = base + OFF_XCC;
    float* xcf    = base + OFF_XCF;
    float* ot     = base + OFF_OT;
    float* of     = base + OFF_OF;
    float* oc     = base + OFF_OC;
    int* counts   = (int*)(base + OFF_COUNTS);
    int* cursor   = (int*)(base + OFF_CURSOR);
    int* rowptr   = (int*)(base + OFF_ROWPTR);
    int* bsum     = (int*)(base + OFF_BSUM);
    int* perm     = (int*)(base + OFF_PERM);
    float* rlin   = base + OFF_RLIN;
    float* rout   = base + OFF_ROUT;
    float* cat0   = base + OFF_CAT0;
    float* cat1   = base + OFF_CAT1;

    // 1. weight prep
    prep_weights<<<(901120 + 255) / 256, 256>>>(lin_w, out_w, Wl0, Wr0, Wl1, Wr1,
                                                rlin, rout, cat0, cat1);

    // 2. CSR build (once; topology layer-invariant)
    const int slotBase[4] = {0, NC, NC + NT, NC + NT + NF};
    CsrB cb{};
    cb.dst[0] = dst_hc; cb.dst[1] = dst_bt; cb.dst[2] = dst_is; cb.dst[3] = dst_pt;
    cb.eStart[0] = 0; cb.eStart[1] = E_HC; cb.eStart[2] = E_HC + E_BT;
    cb.eStart[3] = E_HC + E_BT + E_IS; cb.eStart[4] = NEDGES;
    for (int c = 0; c < 4; c++) cb.slotBase[c] = slotBase[c];

    cudaMemsetAsync(counts, 0, (size_t)NSLOTS * 2 * sizeof(int), 0);  // counts + cursor
    csr_count<<<(NEDGES + 255) / 256, 256>>>(cb, counts);
    const int nScanBlocks = (NSLOTS + 1023) / 1024;   // 645
    scan1<<<nScanBlocks, 1024>>>(counts, rowptr, bsum, NSLOTS);
    scan2<<<1, 1024>>>(bsum, nScanBlocks);
    scan3<<<nScanBlocks, 1024>>>(counts, rowptr, bsum, NSLOTS);
    csr_fill<<<(NEDGES + 255) / 256, 256>>>(cb, rowptr, cursor, perm);

    const int bT = (NT + 127) / 128;   // 157
    const int bC = (NC + 127) / 128;   // 1563
    const int bF = (NF + 127) / 128;   // 313

    // 3. input projections: one grouped launch
    {
        GemmGroups gp{};
        gp.K = 256;
        gp.A[0] = x_table;  gp.B[0] = rlin;          gp.bias[0] = lin_b;       gp.C[0] = feat_t; gp.M[0] = NT; gp.N[0] = 64;
        gp.A[1] = x_column; gp.B[1] = rlin + 16384;  gp.bias[1] = lin_b + 64;  gp.C[1] = feat_c; gp.M[1] = NC; gp.N[1] = 64;
        gp.A[2] = x_fk;     gp.B[2] = rlin + 32768;  gp.bias[2] = lin_b + 128; gp.C[2] = feat_f; gp.M[2] = NF; gp.N[2] = 64;
        for (int g = 0; g < 3; g++) { gp.maskX[g] = 0; gp.shiftX[g] = 0; }
        gp.blockStart[0] = 0; gp.blockStart[1] = bT; gp.blockStart[2] = bT + bC;
        gemm_grouped<1, 1, 1, 64, 4, 2><<<bT + bC + bF, 256, SMEM_BN64>>>(gp);
    }

    const int* srcs[4] = {src_hc, src_bt, src_is, src_pt};

    // per-conv projected-feature slices inside the concatenated buffers
    const float* xls[4] = {xct + 0,   xcc + 256, xcc + 512, xcf + 256};
    const int    lss[4] = {512, 1024, 1024, 512};
    const float* xrs[4] = {xcc + 0,   xct + 256, xcf + 0,   xcc + 768};
    const int    rss[4] = {1024, 512, 512, 1024};

    for (int l = 0; l < 2; l++) {
        const int Kin = (l == 0) ? 64 : 256;
        float* cat = (l == 0) ? cat0 : cat1;
        const float* att = l ? att1 : att0;
        const float* bb  = l ? b1   : b0;

        // 4. concatenated conv projections: one grouped launch
        {
            GemmGroups gp{};
            gp.K = Kin;
            gp.A[0] = feat_t; gp.B[0] = cat;                      gp.bias[0] = nullptr; gp.C[0] = xct; gp.M[0] = NT; gp.N[0] = 512;
            gp.A[1] = feat_c; gp.B[1] = cat + (size_t)Kin * 512;  gp.bias[1] = nullptr; gp.C[1] = xcc; gp.M[1] = NC; gp.N[1] = 1024;
            gp.A[2] = feat_f; gp.B[2] = cat + (size_t)Kin * 1536; gp.bias[2] = nullptr; gp.C[2] = xcf; gp.M[2] = NF; gp.N[2] = 512;
            gp.maskX[0] = 3; gp.shiftX[0] = 2;
            gp.maskX[1] = 7; gp.shiftX[1] = 3;
            gp.maskX[2] = 3; gp.shiftX[2] = 2;
            gp.blockStart[0] = 0;
            gp.blockStart[1] = bT * 4;
            gp.blockStart[2] = bT * 4 + bC * 8;
            gemm_grouped<0, 0, 0, 128, 2, 4><<<bT * 4 + bC * 8 + bF * 4, 256, SMEM_BN128>>>(gp);
        }

        // 5. fused gather (logits + softmax + weighted sum, no atomics)
        GatherB g{};
        for (int c = 0; c < 4; c++) {
            g.srcs[c] = srcs[c];
            g.xl[c] = xls[c]; g.xls[c] = lss[c];
            g.xr[c] = xrs[c]; g.xrs[c] = rss[c];
            g.slotBase[c] = slotBase[c];
        }
        g.att = att;
        g.rowptr = rowptr; g.counts = counts; g.perm = perm;
        gather_b<<<(NROWS + 7) / 8, 256>>>(g, ot, of, oc);

        // 6. fused ELU / combine with bias fold-in
        int tot4 = NT * 64 + NC * 64 + NF * 64;
        elu_comb<<<(tot4 + 255) / 256, 256>>>(ot, oc, of,
                                              bb + 0, bb + 256, bb + 512, bb + 768,
                                              feat_t, feat_c, feat_f);
    }

    // 7. output heads: one grouped launch
    {
        float* out = (float*)d_out;
        GemmGroups gp{};
        gp.K = 256;
        gp.A[0] = feat_t; gp.B[0] = rout;          gp.bias[0] = out_b;       gp.C[0] = out;                           gp.M[0] = NT; gp.N[0] = 256;
        gp.A[1] = feat_c; gp.B[1] = rout + 65536;  gp.bias[1] = out_b + 256; gp.C[1] = out + (size_t)NT * 256;        gp.M[1] = NC; gp.N[1] = 256;
        gp.A[2] = feat_f; gp.B[2] = rout + 131072; gp.bias[2] = out_b + 512; gp.C[2] = out + (size_t)(NT + NC) * 256; gp.M[2] = NF; gp.N[2] = 256;
        for (int g = 0; g < 3; g++) { gp.maskX[g] = 1; gp.shiftX[g] = 1; }
        gp.blockStart[0] = 0; gp.blockStart[1] = bT * 2; gp.blockStart[2] = bT * 2 + bC * 2;
        gemm_grouped<0, 0, 0, 128, 2, 4><<<(bT + bC + bF) * 2, 256, SMEM_BN128>>>(gp);
    }
}

// round 14
// speedup vs baseline: 1.7048x; 1.0583x over previous
#include <cuda_runtime.h>
#include <math.h>
#include <stdint.h>

// ---------------- problem constants ----------------
#define NT 20000
#define NC 200000
#define NF 40000
#define E_HC 200000
#define E_BT 200000
#define E_IS 80000
#define E_PT 80000
#define FH 256
#define NSLOTS (NC + NT + NF + NC)         // 660000 CSR slots (hc,bt,is,pt)
#define NEDGES (E_HC + E_BT + E_IS + E_PT) // 560000
#define NROWS (NT + NF + NC)               // 260000 gather rows

// ---------------- scratch offsets (floats) ----------------
static constexpr size_t OFF_FEAT_T = 0;
static constexpr size_t OFF_FEAT_C = OFF_FEAT_T + (size_t)NT * 256;
static constexpr size_t OFF_FEAT_F = OFF_FEAT_C + (size_t)NC * 256;
static constexpr size_t OFF_XCT    = OFF_FEAT_F + (size_t)NF * 256;   // NT x 512
static constexpr size_t OFF_XCC    = OFF_XCT + (size_t)NT * 512;      // NC x 1024
static constexpr size_t OFF_XCF    = OFF_XCC + (size_t)NC * 1024;     // NF x 512
// CSR int region (counts|cursor adjacent for one memset)
static constexpr size_t OFF_COUNTS = OFF_XCF + (size_t)NF * 512;
static constexpr size_t OFF_CURSOR = OFF_COUNTS + NSLOTS;
static constexpr size_t OFF_ROWPTR = OFF_CURSOR + NSLOTS;
static constexpr size_t OFF_BSUM   = OFF_ROWPTR + NSLOTS;
static constexpr size_t OFF_PERM   = OFF_BSUM + 1024;
static constexpr size_t OFF_RLIN   = OFF_PERM + NEDGES;
static constexpr size_t OFF_ROUT   = OFF_RLIN + 49152;
static constexpr size_t OFF_CAT0   = OFF_ROUT + 196608;
static constexpr size_t OFF_CAT1   = OFF_CAT0 + 131072;
static constexpr size_t SCRATCH_TOTAL = OFF_CAT1 + 524288;

__device__ float g_scratch[SCRATCH_TOTAL];

// ---------------- PTX helpers ----------------
__device__ __forceinline__ void cp_async16(void* dst, const void* src)
{
    uint32_t d = (uint32_t)__cvta_generic_to_shared(dst);
    asm volatile("cp.async.cg.shared.global [%0], [%1], 16;\n" :: "r"(d), "l"(src));
}
__device__ __forceinline__ void cp_commit() { asm volatile("cp.async.commit_group;\n" ::: "memory"); }
__device__ __forceinline__ void cp_wait0()  { asm volatile("cp.async.wait_group 0;\n" ::: "memory"); }
__device__ __forceinline__ void cp_wait1()  { asm volatile("cp.async.wait_group 1;\n" ::: "memory"); }

__device__ __forceinline__ uint32_t cvt_tf32(float x)
{
    uint32_t r; asm("cvt.rna.tf32.f32 %0, %1;" : "=r"(r) : "f"(x)); return r;
}
__device__ __forceinline__ float round_tf32(float x) { return __uint_as_float(cvt_tf32(x)); }

__device__ __forceinline__ void mma_tf32(float* c, const uint32_t* a, const uint32_t* b)
{
    asm volatile("mma.sync.aligned.m16n8k8.row.col.f32.tf32.tf32.f32 "
                 "{%0,%1,%2,%3}, {%4,%5,%6,%7}, {%8,%9}, {%0,%1,%2,%3};"
                 : "+f"(c[0]), "+f"(c[1]), "+f"(c[2]), "+f"(c[3])
                 : "r"(a[0]), "r"(a[1]), "r"(a[2]), "r"(a[3]), "r"(b[0]), "r"(b[1]));
}

// ---------------- grouped tf32 GEMM (proven R8/R11 version) ----------------
struct GemmGroups {
    const float* A[3]; const float* B[3]; const float* bias[3]; float* C[3];
    int M[3]; int N[3];
    int maskX[3]; int shiftX[3];
    int blockStart[3];
    int K;
};

template<int CVT_A, int ACT, int ROUND_OUT, int BN, int WARPS_M, int WARPS_N>
__global__ void __launch_bounds__(256, 2)
gemm_grouped(GemmGroups gg)
{
    constexpr int BM = 128, BK = 32;
    constexpr int BKP = 36;
    constexpr int BNP = BN + 8;
    constexpr int WM = BM / WARPS_M, WN = BN / WARPS_N;
    constexpr int MI = WM / 16, NI = WN / 8;
    constexpr int A_STAGE = BM * BKP;
    constexpr int B_STAGE = BK * BNP;
    constexpr int STAGES = 3;

    extern __shared__ float sm[];
    float* Asm = sm;
    float* Bsm = sm + STAGES * A_STAGE;

    const int bid = blockIdx.x;
    const int g = (bid >= gg.blockStart[1]) + (bid >= gg.blockStart[2]);
    const int local = bid - gg.blockStart[g];
    const int tileX = local & gg.maskX[g];
    const int tileY = local >> gg.shiftX[g];

    const float* __restrict__ A = gg.A[g];
    const float* __restrict__ B = gg.B[g];
    const float* __restrict__ bias = gg.bias[g];
    float* __restrict__ C = gg.C[g];
    const int M = gg.M[g], N = gg.N[g], K = gg.K;
    const int rowBase = tileY * BM;
    const int colBase = tileX * BN;

    const int tid  = threadIdx.x;
    const int lane = tid & 31;
    const int warp = tid >> 5;
    const int gq   = lane >> 2;
    const int tig  = lane & 3;
    const int warpM = warp % WARPS_M;
    const int warpN = warp / WARPS_M;

    float acc[MI][NI][4];
#pragma unroll
    for (int mi = 0; mi < MI; mi++)
#pragma unroll
        for (int ni = 0; ni < NI; ni++)
#pragma unroll
            for (int q = 0; q < 4; q++) acc[mi][ni][q] = 0.f;

    auto load_tile = [&](int t, int s) {
#pragma unroll
        for (int i = 0; i < 4; i++) {
            int li = tid + i * 256;
            int m = li >> 3;
            int k4 = (li & 7) << 2;
            int gm = rowBase + m;
            if (gm >= M) gm = M - 1;
            cp_async16(Asm + s * A_STAGE + m * BKP + k4,
                       A + (size_t)gm * K + t * BK + k4);
        }
#pragma unroll
        for (int i = 0; i < (BK * BN) / 1024; i++) {
            int li = tid + i * 256;
            int k = li / (BN / 4);
            int n4 = (li % (BN / 4)) << 2;
            cp_async16(Bsm + s * B_STAGE + k * BNP + n4,
                       B + (size_t)(t * BK + k) * N + colBase + n4);
        }
        cp_commit();
    };

    const int nT = K / BK;
    load_tile(0, 0);
    if (nT > 1) load_tile(1, 1);

    for (int t = 0; t < nT; t++) {
        if (t + 1 < nT) cp_wait1(); else cp_wait0();
        __syncthreads();
        if (t + 2 < nT) load_tile(t + 2, (t + 2) % STAGES);

        const float* Asb = Asm + (t % STAGES) * A_STAGE;
        const float* Bsb = Bsm + (t % STAGES) * B_STAGE;
#pragma unroll
        for (int k8 = 0; k8 < BK / 8; k8++) {
            const int kk = k8 * 8;
            uint32_t a[MI][4], b[NI][2];
#pragma unroll
            for (int mi = 0; mi < MI; mi++) {
                const float* ap = Asb + (warpM * WM + mi * 16 + gq) * BKP + kk + tig;
                if (CVT_A) {
                    a[mi][0] = cvt_tf32(ap[0]);
                    a[mi][1] = cvt_tf32(ap[8 * BKP]);
                    a[mi][2] = cvt_tf32(ap[4]);
                    a[mi][3] = cvt_tf32(ap[8 * BKP + 4]);
                } else {
                    a[mi][0] = __float_as_uint(ap[0]);
                    a[mi][1] = __float_as_uint(ap[8 * BKP]);
                    a[mi][2] = __float_as_uint(ap[4]);
                    a[mi][3] = __float_as_uint(ap[8 * BKP + 4]);
                }
            }
#pragma unroll
            for (int ni = 0; ni < NI; ni++) {
                const float* bp = Bsb + (kk + tig) * BNP + warpN * WN + ni * 8 + gq;
                b[ni][0] = __float_as_uint(bp[0]);
                b[ni][1] = __float_as_uint(bp[4 * BNP]);
            }
#pragma unroll
            for (int mi = 0; mi < MI; mi++)
#pragma unroll
                for (int ni = 0; ni < NI; ni++)
                    mma_tf32(acc[mi][ni], a[mi], b[ni]);
        }
    }

#pragma unroll
    for (int mi = 0; mi < MI; mi++) {
        int row0 = rowBase + warpM * WM + mi * 16 + gq;
#pragma unroll
        for (int ni = 0; ni < NI; ni++) {
            int col = colBase + warpN * WN + ni * 8 + tig * 2;
            float bx = 0.f, by = 0.f;
            if (bias) { bx = bias[col]; by = bias[col + 1]; }
            float2 v;
            v.x = acc[mi][ni][0] + bx;
            v.y = acc[mi][ni][1] + by;
            if (ACT == 1) {
                v.x = v.x > 0.f ? v.x : 0.01f * v.x;
                v.y = v.y > 0.f ? v.y : 0.01f * v.y;
            }
            if (ROUND_OUT) { v.x = round_tf32(v.x); v.y = round_tf32(v.y); }
            if (row0 < M) *(float2*)(C + (size_t)row0 * N + col) = v;
            v.x = acc[mi][ni][2] + bx;
            v.y = acc[mi][ni][3] + by;
            if (ACT == 1) {
                v.x = v.x > 0.f ? v.x : 0.01f * v.x;
                v.y = v.y > 0.f ? v.y : 0.01f * v.y;
            }
            if (ROUND_OUT) { v.x = round_tf32(v.x); v.y = round_tf32(v.y); }
            if (row0 + 8 < M) *(float2*)(C + (size_t)(row0 + 8) * N + col) = v;
        }
    }
}

#define SMEM_BN128 (3 * (128*36 + 32*136) * 4)
#define SMEM_BN64  (3 * (128*36 + 32*72)  * 4)

// ---------------- weight prep: round + concat ----------------
__device__ float cat_src(int i, int K, const float* Wl, const float* Wr)
{
    int tN = K * 512, cN = K * 1024;
    if (i < tN) {
        int k = i >> 9, j = i & 511;
        return (j < 256) ? Wl[(0 * K + k) * 256 + j] : Wr[(1 * K + k) * 256 + (j - 256)];
    }
    i -= tN;
    if (i < cN) {
        int k = i >> 10, j = i & 1023;
        int c = j >> 8, col = j & 255;
        const float* p = (c == 0) ? Wr + (0 * K + k) * 256
                       : (c == 1) ? Wl + (1 * K + k) * 256
                       : (c == 2) ? Wl + (2 * K + k) * 256
                                  : Wr + (3 * K + k) * 256;
        return p[col];
    }
    i -= cN;
    int k = i >> 9, j = i & 511;
    return (j < 256) ? Wr[(2 * K + k) * 256 + j] : Wl[(3 * K + k) * 256 + (j - 256)];
}

__global__ void prep_weights(const float* __restrict__ lw, const float* __restrict__ ow,
                             const float* __restrict__ wl0, const float* __restrict__ wr0,
                             const float* __restrict__ wl1, const float* __restrict__ wr1,
                             float* __restrict__ rlin, float* __restrict__ rout,
                             float* __restrict__ cat0, float* __restrict__ cat1)
{
    int i = blockIdx.x * blockDim.x + threadIdx.x;
    if (i < 49152) { rlin[i] = round_tf32(lw[i]); return; }
    i -= 49152;
    if (i < 196608) { rout[i] = round_tf32(ow[i]); return; }
    i -= 196608;
    if (i < 131072) { cat0[i] = round_tf32(cat_src(i, 64, wl0, wr0)); return; }
    i -= 131072;
    if (i < 524288) cat1[i] = round_tf32(cat_src(i, 256, wl1, wr1));
}

// ---------------- CSR build (topology layer-invariant; built once) -----
struct CsrB {
    const int* dst[4];
    int eStart[5];
    int slotBase[4];
};

__global__ void csr_count(CsrB cb, int* __restrict__ counts)
{
    int i = blockIdx.x * 256 + threadIdx.x;
    if (i >= cb.eStart[4]) return;
    int c = (i >= cb.eStart[2]) ? ((i >= cb.eStart[3]) ? 3 : 2)
                                : ((i >= cb.eStart[1]) ? 1 : 0);
    int e = i - cb.eStart[c];
    atomicAdd(&counts[cb.slotBase[c] + cb.dst[c][e]], 1);
}

__global__ void scan1(const int* __restrict__ cnt, int* __restrict__ incl,
                      int* __restrict__ bsum, int n)
{
    __shared__ int sh[1024];
    int i = blockIdx.x * 1024 + threadIdx.x;
    sh[threadIdx.x] = (i < n) ? cnt[i] : 0;
    __syncthreads();
#pragma unroll
    for (int o = 1; o < 1024; o <<= 1) {
        int t = (threadIdx.x >= o) ? sh[threadIdx.x - o] : 0;
        __syncthreads();
        sh[threadIdx.x] += t;
        __syncthreads();
    }
    if (i < n) incl[i] = sh[threadIdx.x];
    if (threadIdx.x == 1023) bsum[blockIdx.x] = sh[1023];
}

__global__ void scan2(int* __restrict__ bsum, int nb)
{
    __shared__ int sh[1024];
    int t = threadIdx.x;
    sh[t] = (t < nb) ? bsum[t] : 0;
    __syncthreads();
#pragma unroll
    for (int o = 1; o < 1024; o <<= 1) {
        int v = (t >= o) ? sh[t - o] : 0;
        __syncthreads();
        sh[t] += v;
        __syncthreads();
    }
    if (t < nb) bsum[t] = sh[t];
}

__global__ void scan3(const int* __restrict__ cnt, int* __restrict__ ptr,
                      const int* __restrict__ bsum, int n)
{
    int i = blockIdx.x * 1024 + threadIdx.x;
    if (i >= n) return;
    int off = blockIdx.x ? bsum[blockIdx.x - 1] : 0;
    ptr[i] = ptr[i] + off - cnt[i];   // inclusive -> exclusive + block offset
}

__global__ void csr_fill(CsrB cb, const int* __restrict__ rowptr,
                         int* __restrict__ cursor, int* __restrict__ perm)
{
    int i = blockIdx.x * 256 + threadIdx.x;
    if (i >= cb.eStart[4]) return;
    int c = (i >= cb.eStart[2]) ? ((i >= cb.eStart[3]) ? 3 : 2)
                                : ((i >= cb.eStart[1]) ? 1 : 0);
    int e = i - cb.eStart[c];
    int slot = cb.slotBase[c] + cb.dst[c][e];
    int pos = atomicAdd(&cursor[slot], 1);
    perm[rowptr[slot] + pos] = e;
}

// ---------------- fused gather: logits + softmax + sum + ELU epilogue -----
// One warp per dst row. Computes the GATv2 logit inline against the
// register-cached xr[dst] row + att (z = exp(logit), no max shift: logits
// O(1)), accumulates z * xl, normalizes, then applies the HeteroConv
// combine (bias + optional mean) + ELU + tf32 rounding and writes the
// next-layer feature row directly. The elu_comb pass and the ot/of/oc
// intermediates are gone.
struct GatherB {
    const int* srcs[4];
    const float* xl[4]; int xls[4];
    const float* xr[4]; int xrs[4];
    const float* att;                 // conv c at att + c*256
    const float* bias;                // conv c at bias + c*256
    const int* rowptr; const int* counts; const int* perm;
    int slotBase[4];
};

__device__ __forceinline__ float eluf(float x) { return x > 0.f ? x : expm1f(x); }

__device__ __forceinline__ void accum_fused(int conv, int slot, int d,
                                            const GatherB& g, float* acc, int lane)
{
    int cnt = g.counts[slot];
    if (cnt == 0) return;
    int start = g.rowptr[slot];

    const float4* pr = (const float4*)(g.xr[conv] + (size_t)d * g.xrs[conv]) + lane * 2;
    float4 r0 = pr[0], r1 = pr[1];
    const float4* pa = (const float4*)(g.att + conv * 256) + lane * 2;
    float4 a0 = pa[0], a1 = pa[1];

    const int* sr = g.srcs[conv];
    const float* xlp = g.xl[conv];
    int stride = g.xls[conv];

    float den = 0.f;
    float num[8];
#pragma unroll
    for (int q = 0; q < 8; q++) num[q] = 0.f;

    for (int j = 0; j < cnt; j++) {
        int e = g.perm[start + j];
        const float4* pl = (const float4*)(xlp + (size_t)sr[e] * stride) + lane * 2;
        float4 l0 = pl[0], l1 = pl[1];
        float t = 0.f, v;
        v = l0.x + r0.x; v = v > 0.f ? v : 0.2f * v; t += v * a0.x;
        v = l0.y + r0.y; v = v > 0.f ? v : 0.2f * v; t += v * a0.y;
        v = l0.z + r0.z; v = v > 0.f ? v : 0.2f * v; t += v * a0.z;
        v = l0.w + r0.w; v = v > 0.f ? v : 0.2f * v; t += v * a0.w;
        v = l1.x + r1.x; v = v > 0.f ? v : 0.2f * v; t += v * a1.x;
        v = l1.y + r1.y; v = v > 0.f ? v : 0.2f * v; t += v * a1.y;
        v = l1.z + r1.z; v = v > 0.f ? v : 0.2f * v; t += v * a1.z;
        v = l1.w + r1.w; v = v > 0.f ? v : 0.2f * v; t += v * a1.w;
        t += __shfl_xor_sync(0xffffffffu, t, 1);
        t += __shfl_xor_sync(0xffffffffu, t, 2);
        t += __shfl_xor_sync(0xffffffffu, t, 4);   // full head logit in all 8 lanes
        float z = expf(t);
        den += z;
        num[0] += z * l0.x; num[1] += z * l0.y; num[2] += z * l0.z; num[3] += z * l0.w;
        num[4] += z * l1.x; num[5] += z * l1.y; num[6] += z * l1.z; num[7] += z * l1.w;
    }
    float inv = 1.f / den;
#pragma unroll
    for (int q = 0; q < 8; q++) acc[q] += num[q] * inv;
}

__global__ void gather_b(GatherB g, float* __restrict__ ft, float* __restrict__ fc,
                         float* __restrict__ ff)
{
    int r = blockIdx.x * 8 + (threadIdx.x >> 5);
    if (r >= NROWS) return;
    int lane = threadIdx.x & 31;
    float acc[8];
#pragma unroll
    for (int q = 0; q < 8; q++) acc[q] = 0.f;
    float* out;
    float res[8];
    if (r < NT) {                                  // bt -> table rows
        accum_fused(1, g.slotBase[1] + r, r, g, acc, lane);
        const float4* pb = (const float4*)(g.bias + 256) + lane * 2;
        float4 b0 = pb[0], b1 = pb[1];
        res[0] = acc[0] + b0.x; res[1] = acc[1] + b0.y; res[2] = acc[2] + b0.z; res[3] = acc[3] + b0.w;
        res[4] = acc[4] + b1.x; res[5] = acc[5] + b1.y; res[6] = acc[6] + b1.z; res[7] = acc[7] + b1.w;
        out = ft + (size_t)r * 256;
    } else if (r < NT + NF) {                      // is -> fk rows
        int d = r - NT;
        accum_fused(2, g.slotBase[2] + d, d, g, acc, lane);
        const float4* pb = (const float4*)(g.bias + 512) + lane * 2;
        float4 b0 = pb[0], b1 = pb[1];
        res[0] = acc[0] + b0.x; res[1] = acc[1] + b0.y; res[2] = acc[2] + b0.z; res[3] = acc[3] + b0.w;
        res[4] = acc[4] + b1.x; res[5] = acc[5] + b1.y; res[6] = acc[6] + b1.z; res[7] = acc[7] + b1.w;
        out = ff + (size_t)d * 256;
    } else {                                       // hc + pt -> column rows (mean)
        int d = r - NT - NF;
        accum_fused(0, g.slotBase[0] + d, d, g, acc, lane);
        accum_fused(3, g.slotBase[3] + d, d, g, acc, lane);
        const float4* ph = (const float4*)(g.bias + 0) + lane * 2;
        const float4* pp = (const float4*)(g.bias + 768) + lane * 2;
        float4 h0 = ph[0], h1 = ph[1], p0 = pp[0], p1 = pp[1];
        res[0] = 0.5f * (acc[0] + h0.x + p0.x); res[1] = 0.5f * (acc[1] + h0.y + p0.y);
        res[2] = 0.5f * (acc[2] + h0.z + p0.z); res[3] = 0.5f * (acc[3] + h0.w + p0.w);
        res[4] = 0.5f * (acc[4] + h1.x + p1.x); res[5] = 0.5f * (acc[5] + h1.y + p1.y);
        res[6] = 0.5f * (acc[6] + h1.z + p1.z); res[7] = 0.5f * (acc[7] + h1.w + p1.w);
        out = fc + (size_t)d * 256;
    }
#pragma unroll
    for (int q = 0; q < 8; q++) res[q] = round_tf32(eluf(res[q]));
    float4* po = (float4*)out + lane * 2;
    po[0] = make_float4(res[0], res[1], res[2], res[3]);
    po[1] = make_float4(res[4], res[5], res[6], res[7]);
}

// ---------------- host orchestration ----------------
extern "C" void kernel_launch(void* const* d_in, const int* in_sizes, int n_in,
                              void* d_out, int out_size)
{
    (void)in_sizes; (void)n_in; (void)out_size;
    const float* x_table  = (const float*)d_in[0];
    const float* x_column = (const float*)d_in[1];
    const float* x_fk     = (const float*)d_in[2];
    const float* lin_w    = (const float*)d_in[3];
    const float* lin_b    = (const float*)d_in[4];
    const float* out_w    = (const float*)d_in[5];
    const float* out_b    = (const float*)d_in[6];
    const float* Wl0      = (const float*)d_in[7];
    const float* Wr0      = (const float*)d_in[8];
    const float* att0     = (const float*)d_in[9];
    const float* b0       = (const float*)d_in[10];
    const float* Wl1      = (const float*)d_in[11];
    const float* Wr1      = (const float*)d_in[12];
    const float* att1     = (const float*)d_in[13];
    const float* b1       = (const float*)d_in[14];
    const int* src_hc = (const int*)d_in[15];
    const int* dst_hc = (const int*)d_in[16];
    const int* src_bt = (const int*)d_in[17];
    const int* dst_bt = (const int*)d_in[18];
    const int* src_is = (const int*)d_in[19];
    const int* dst_is = (const int*)d_in[20];
    const int* src_pt = (const int*)d_in[21];
    const int* dst_pt = (const int*)d_in[22];

    cudaFuncSetAttribute((const void*)gemm_grouped<1, 1, 1, 64, 4, 2>,
                         cudaFuncAttributeMaxDynamicSharedMemorySize, SMEM_BN64);
    cudaFuncSetAttribute((const void*)gemm_grouped<0, 0, 0, 128, 2, 4>,
                         cudaFuncAttributeMaxDynamicSharedMemorySize, SMEM_BN128);

    float* base = nullptr;
    cudaGetSymbolAddress((void**)&base, g_scratch);
    float* feat_t = base + OFF_FEAT_T;
    float* feat_c = base + OFF_FEAT_C;
    float* feat_f = base + OFF_FEAT_F;
    float* xct    = base + OFF_XCT;
    float* xcc    = base + OFF_XCC;
    float* xcf    = base + OFF_XCF;
    int* counts   = (int*)(base + OFF_COUNTS);
    int* cursor   = (int*)(base + OFF_CURSOR);
    int* rowptr   = (int*)(base + OFF_ROWPTR);
    int* bsum     = (int*)(base + OFF_BSUM);
    int* perm     = (int*)(base + OFF_PERM);
    float* rlin   = base + OFF_RLIN;
    float* rout   = base + OFF_ROUT;
    float* cat0   = base + OFF_CAT0;
    float* cat1   = base + OFF_CAT1;

    // 1. weight prep
    prep_weights<<<(901120 + 255) / 256, 256>>>(lin_w, out_w, Wl0, Wr0, Wl1, Wr1,
                                                rlin, rout, cat0, cat1);

    // 2. CSR build (once; topology layer-invariant)
    const int slotBase[4] = {0, NC, NC + NT, NC + NT + NF};
    CsrB cb{};
    cb.dst[0] = dst_hc; cb.dst[1] = dst_bt; cb.dst[2] = dst_is; cb.dst[3] = dst_pt;
    cb.eStart[0] = 0; cb.eStart[1] = E_HC; cb.eStart[2] = E_HC + E_BT;
    cb.eStart[3] = E_HC + E_BT + E_IS; cb.eStart[4] = NEDGES;
    for (int c = 0; c < 4; c++) cb.slotBase[c] = slotBase[c];

    cudaMemsetAsync(counts, 0, (size_t)NSLOTS * 2 * sizeof(int), 0);  // counts + cursor
    csr_count<<<(NEDGES + 255) / 256, 256>>>(cb, counts);
    const int nScanBlocks = (NSLOTS + 1023) / 1024;   // 645
    scan1<<<nScanBlocks, 1024>>>(counts, rowptr, bsum, NSLOTS);
    scan2<<<1, 1024>>>(bsum, nScanBlocks);
    scan3<<<nScanBlocks, 1024>>>(counts, rowptr, bsum, NSLOTS);
    csr_fill<<<(NEDGES + 255) / 256, 256>>>(cb, rowptr, cursor, perm);

    const int bT = (NT + 127) / 128;   // 157
    const int bC = (NC + 127) / 128;   // 1563
    const int bF = (NF + 127) / 128;   // 313

    // 3. input projections: one grouped launch
    {
        GemmGroups gp{};
        gp.K = 256;
        gp.A[0] = x_table;  gp.B[0] = rlin;          gp.bias[0] = lin_b;       gp.C[0] = feat_t; gp.M[0] = NT; gp.N[0] = 64;
        gp.A[1] = x_column; gp.B[1] = rlin + 16384;  gp.bias[1] = lin_b + 64;  gp.C[1] = feat_c; gp.M[1] = NC; gp.N[1] = 64;
        gp.A[2] = x_fk;     gp.B[2] = rlin + 32768;  gp.bias[2] = lin_b + 128; gp.C[2] = feat_f; gp.M[2] = NF; gp.N[2] = 64;
        for (int g = 0; g < 3; g++) { gp.maskX[g] = 0; gp.shiftX[g] = 0; }
        gp.blockStart[0] = 0; gp.blockStart[1] = bT; gp.blockStart[2] = bT + bC;
        gemm_grouped<1, 1, 1, 64, 4, 2><<<bT + bC + bF, 256, SMEM_BN64>>>(gp);
    }

    const int* srcs[4] = {src_hc, src_bt, src_is, src_pt};

    // per-conv projected-feature slices inside the concatenated buffers
    const float* xls[4] = {xct + 0,   xcc + 256, xcc + 512, xcf + 256};
    const int    lss[4] = {512, 1024, 1024, 512};
    const float* xrs[4] = {xcc + 0,   xct + 256, xcf + 0,   xcc + 768};
    const int    rss[4] = {1024, 512, 512, 1024};

    for (int l = 0; l < 2; l++) {
        const int Kin = (l == 0) ? 64 : 256;
        float* cat = (l == 0) ? cat0 : cat1;
        const float* att = l ? att1 : att0;
        const float* bb  = l ? b1   : b0;

        // 4. concatenated conv projections: one grouped launch
        {
            GemmGroups gp{};
            gp.K = Kin;
            gp.A[0] = feat_t; gp.B[0] = cat;                      gp.bias[0] = nullptr; gp.C[0] = xct; gp.M[0] = NT; gp.N[0] = 512;
            gp.A[1] = feat_c; gp.B[1] = cat + (size_t)Kin * 512;  gp.bias[1] = nullptr; gp.C[1] = xcc; gp.M[1] = NC; gp.N[1] = 1024;
            gp.A[2] = feat_f; gp.B[2] = cat + (size_t)Kin * 1536; gp.bias[2] = nullptr; gp.C[2] = xcf; gp.M[2] = NF; gp.N[2] = 512;
            gp.maskX[0] = 3; gp.shiftX[0] = 2;
            gp.maskX[1] = 7; gp.shiftX[1] = 3;
            gp.maskX[2] = 3; gp.shiftX[2] = 2;
            gp.blockStart[0] = 0;
            gp.blockStart[1] = bT * 4;
            gp.blockStart[2] = bT * 4 + bC * 8;
            gemm_grouped<0, 0, 0, 128, 2, 4><<<bT * 4 + bC * 8 + bF * 4, 256, SMEM_BN128>>>(gp);
        }

        // 5. fused gather + ELU/combine epilogue -> next-layer features
        GatherB g{};
        for (int c = 0; c < 4; c++) {
            g.srcs[c] = srcs[c];
            g.xl[c] = xls[c]; g.xls[c] = lss[c];
            g.xr[c] = xrs[c]; g.xrs[c] = rss[c];
            g.slotBase[c] = slotBase[c];
        }
        g.att = att;
        g.bias = bb;
        g.rowptr = rowptr; g.counts = counts; g.perm = perm;
        gather_b<<<(NROWS + 7) / 8, 256>>>(g, feat_t, feat_c, feat_f);
    }

    // 6. output heads: one grouped launch
    {
        float* out = (float*)d_out;
        GemmGroups gp{};
        gp.K = 256;
        gp.A[0] = feat_t; gp.B[0] = rout;          gp.bias[0] = out_b;       gp.C[0] = out;                           gp.M[0] = NT; gp.N[0] = 256;
        gp.A[1] = feat_c; gp.B[1] = rout + 65536;  gp.bias[1] = out_b + 256; gp.C[1] = out + (size_t)NT * 256;        gp.M[1] = NC; gp.N[1] = 256;
        gp.A[2] = feat_f; gp.B[2] = rout + 131072; gp.bias[2] = out_b + 512; gp.C[2] = out + (size_t)(NT + NC) * 256; gp.M[2] = NF; gp.N[2] = 256;
        for (int g = 0; g < 3; g++) { gp.maskX[g] = 1; gp.shiftX[g] = 1; }
        gp.blockStart[0] = 0; gp.blockStart[1] = bT * 2; gp.blockStart[2] = bT * 2 + bC * 2;
        gemm_grouped<0, 0, 0, 128, 2, 4><<<(bT + bC + bF) * 2, 256, SMEM_BN128>>>(gp);
    }
}

// round 16
// speedup vs baseline: 2.1372x; 1.2537x over previous
#include <cuda_runtime.h>
#include <cuda_fp16.h>
#include <math.h>
#include <stdint.h>

// ---------------- problem constants ----------------
#define NT 20000
#define NC 200000
#define NF 40000
#define E_HC 200000
#define E_BT 200000
#define E_IS 80000
#define E_PT 80000
#define FH 256
#define NSLOTS (NC + NT + NF + NC)
#define NEDGES (E_HC + E_BT + E_IS + E_PT)
#define NROWS (NT + NF + NC)

// ---------------- scratch offsets (float units) ----------------
// half regions occupy count/2 float slots; all offsets multiple of 4 floats (16B).
static constexpr size_t OFF_FEAT_T = 0;                                   // half NT*256
static constexpr size_t OFF_FEAT_C = OFF_FEAT_T + (size_t)NT * 128;       // half NC*256
static constexpr size_t OFF_FEAT_F = OFF_FEAT_C + (size_t)NC * 128;      // half NF*256
static constexpr size_t OFF_HXT    = OFF_FEAT_F + (size_t)NF * 128;      // half NT*256
static constexpr size_t OFF_HXC    = OFF_HXT + (size_t)NT * 128;
static constexpr size_t OFF_HXF    = OFF_HXC + (size_t)NC * 128;
static constexpr size_t OFF_XCT    = OFF_HXF + (size_t)NF * 128;         // fp32 NT x 512
static constexpr size_t OFF_XCC    = OFF_XCT + (size_t)NT * 512;         // fp32 NC x 1024
static constexpr size_t OFF_XCF    = OFF_XCC + (size_t)NC * 1024;        // fp32 NF x 512
static constexpr size_t OFF_COUNTS = OFF_XCF + (size_t)NF * 512;
static constexpr size_t OFF_CURSOR = OFF_COUNTS + NSLOTS;
static constexpr size_t OFF_ROWPTR = OFF_CURSOR + NSLOTS;
static constexpr size_t OFF_BSUM   = OFF_ROWPTR + NSLOTS;
static constexpr size_t OFF_PERM   = OFF_BSUM + 1024;
static constexpr size_t OFF_RLIN   = OFF_PERM + NEDGES;                  // half 49152
static constexpr size_t OFF_ROUT   = OFF_RLIN + 24576;                   // half 196608
static constexpr size_t OFF_CAT0   = OFF_ROUT + 98304;                   // half 131072
static constexpr size_t OFF_CAT1   = OFF_CAT0 + 65536;                   // half 524288
static constexpr size_t SCRATCH_TOTAL = OFF_CAT1 + 262144;

__device__ float g_scratch[SCRATCH_TOTAL];

// ---------------- PTX helpers ----------------
__device__ __forceinline__ void cp_async16(void* dst, const void* src)
{
    uint32_t d = (uint32_t)__cvta_generic_to_shared(dst);
    asm volatile("cp.async.cg.shared.global [%0], [%1], 16;\n" :: "r"(d), "l"(src));
}
__device__ __forceinline__ void cp_commit() { asm volatile("cp.async.commit_group;\n" ::: "memory"); }
__device__ __forceinline__ void cp_wait0()  { asm volatile("cp.async.wait_group 0;\n" ::: "memory"); }
__device__ __forceinline__ void cp_wait1()  { asm volatile("cp.async.wait_group 1;\n" ::: "memory"); }

__device__ __forceinline__ void mma_f16(float* c, const uint32_t* a, const uint32_t* b)
{
    asm volatile("mma.sync.aligned.m16n8k16.row.col.f32.f16.f16.f32 "
                 "{%0,%1,%2,%3}, {%4,%5,%6,%7}, {%8,%9}, {%0,%1,%2,%3};"
                 : "+f"(c[0]), "+f"(c[1]), "+f"(c[2]), "+f"(c[3])
                 : "r"(a[0]), "r"(a[1]), "r"(a[2]), "r"(a[3]), "r"(b[0]), "r"(b[1]));
}

// ---------------- grouped fp16 GEMM ----------------
// A [M,K] half row-major. B [N,K] half row-major (K-contiguous).
// acc fp32. Output fp32 (OUT_HALF=0) or half (OUT_HALF=1, optional lrelu).
struct GemmGroups {
    const __half* A[3]; const __half* B[3]; const float* bias[3]; void* C[3];
    int M[3]; int N[3];
    int maskX[3]; int shiftX[3];
    int blockStart[3];
    int K;
};

template<int ACT, int OUT_HALF, int BN, int WARPS_M, int WARPS_N>
__global__ void __launch_bounds__(256, 2)
gemm_h(GemmGroups gg)
{
    constexpr int BM = 128, BK = 32;
    constexpr int BKP = 40;   // halves; row stride 80B = 20 banks -> conflict-free
    constexpr int WM = BM / WARPS_M, WN = BN / WARPS_N;
    constexpr int MI = WM / 16, NI = WN / 8;
    constexpr int A_STAGE = BM * BKP;        // halves
    constexpr int B_STAGE = BN * BKP;
    constexpr int STAGES = 3;

    extern __shared__ __half smh[];
    __half* Asm = smh;
    __half* Bsm = smh + STAGES * A_STAGE;

    const int bid = blockIdx.x;
    const int g = (bid >= gg.blockStart[1]) + (bid >= gg.blockStart[2]);
    const int local = bid - gg.blockStart[g];
    const int tileX = local & gg.maskX[g];
    const int tileY = local >> gg.shiftX[g];

    const __half* __restrict__ A = gg.A[g];
    const __half* __restrict__ Bt = gg.B[g];
    const float* __restrict__ bias = gg.bias[g];
    const int M = gg.M[g], N = gg.N[g], K = gg.K;
    const int rowBase = tileY * BM;
    const int colBase = tileX * BN;

    const int tid  = threadIdx.x;
    const int lane = tid & 31;
    const int warp = tid >> 5;
    const int gq   = lane >> 2;
    const int tig  = lane & 3;
    const int warpM = warp % WARPS_M;
    const int warpN = warp / WARPS_M;

    float acc[MI][NI][4];
#pragma unroll
    for (int mi = 0; mi < MI; mi++)
#pragma unroll
        for (int ni = 0; ni < NI; ni++)
#pragma unroll
            for (int q = 0; q < 4; q++) acc[mi][ni][q] = 0.f;

    auto load_tile = [&](int t, int s) {
        // A: BM x BK halves = 512 x 16B chunks, 2 per thread
#pragma unroll
        for (int i = 0; i < 2; i++) {
            int li = tid + i * 256;
            int m = li >> 2;
            int c8 = (li & 3) << 3;          // half offset within row
            int gm = rowBase + m;
            if (gm >= M) gm = M - 1;
            cp_async16(Asm + s * A_STAGE + m * BKP + c8,
                       A + (size_t)gm * K + t * BK + c8);
        }
        // B: BN x BK halves = BN*4 chunks
#pragma unroll
        for (int i = 0; i < BN / 64; i++) {
            int li = tid + i * 256;
            int n = li >> 2;
            int c8 = (li & 3) << 3;
            cp_async16(Bsm + s * B_STAGE + n * BKP + c8,
                       Bt + (size_t)(colBase + n) * K + t * BK + c8);
        }
        cp_commit();
    };

    const int nT = K / BK;
    load_tile(0, 0);
    if (nT > 1) load_tile(1, 1);

    for (int t = 0; t < nT; t++) {
        if (t + 1 < nT) cp_wait1(); else cp_wait0();
        __syncthreads();
        if (t + 2 < nT) load_tile(t + 2, (t + 2) % STAGES);

        const __half* Asb = Asm + (t % STAGES) * A_STAGE;
        const __half* Bsb = Bsm + (t % STAGES) * B_STAGE;
#pragma unroll
        for (int k16 = 0; k16 < BK / 16; k16++) {
            const int kk = k16 * 16;
            uint32_t a[MI][4], b[NI][2];
#pragma unroll
            for (int mi = 0; mi < MI; mi++) {
                const __half* ap = Asb + (warpM * WM + mi * 16 + gq) * BKP + kk + 2 * tig;
                a[mi][0] = *(const uint32_t*)(ap);
                a[mi][1] = *(const uint32_t*)(ap + 8 * BKP);
                a[mi][2] = *(const uint32_t*)(ap + 8);
                a[mi][3] = *(const uint32_t*)(ap + 8 * BKP + 8);
            }
#pragma unroll
            for (int ni = 0; ni < NI; ni++) {
                const __half* bp = Bsb + (warpN * WN + ni * 8 + gq) * BKP + kk + 2 * tig;
                b[ni][0] = *(const uint32_t*)(bp);
                b[ni][1] = *(const uint32_t*)(bp + 8);
            }
#pragma unroll
            for (int mi = 0; mi < MI; mi++)
#pragma unroll
                for (int ni = 0; ni < NI; ni++)
                    mma_f16(acc[mi][ni], a[mi], b[ni]);
        }
    }

#pragma unroll
    for (int mi = 0; mi < MI; mi++) {
        int row0 = rowBase + warpM * WM + mi * 16 + gq;
#pragma unroll
        for (int ni = 0; ni < NI; ni++) {
            int col = colBase + warpN * WN + ni * 8 + tig * 2;
            float bx = 0.f, by = 0.f;
            if (bias) { bx = bias[col]; by = bias[col + 1]; }
#pragma unroll
            for (int h = 0; h < 2; h++) {
                int row = row0 + h * 8;
                float2 v;
                v.x = acc[mi][ni][h * 2 + 0] + bx;
                v.y = acc[mi][ni][h * 2 + 1] + by;
                if (ACT == 1) {
                    v.x = v.x > 0.f ? v.x : 0.01f * v.x;
                    v.y = v.y > 0.f ? v.y : 0.01f * v.y;
                }
                if (row < M) {
                    if (OUT_HALF) {
                        __half2 hv = __floats2half2_rn(v.x, v.y);
                        *(__half2*)((__half*)gg.C[g] + (size_t)row * N + col) = hv;
                    } else {
                        *(float2*)((float*)gg.C[g] + (size_t)row * N + col) = v;
                    }
                }
            }
        }
    }
}

#define SMEMH_BN128 (3 * (128*40 + 128*40) * 2)   // 61440
#define SMEMH_BN64  (3 * (128*40 + 64*40)  * 2)   // 46080

// ---------------- weight prep: half + transpose + concat ----------------
// catT[j][k] layout (validated in R9): j = concatenated output column.
__device__ float catT_src(int j, int k, int K, const float* Wl, const float* Wr)
{
    if (j < 512) {
        return (j < 256) ? Wl[(size_t)k * 256 + j]
                         : Wr[((size_t)K + k) * 256 + (j - 256)];
    }
    if (j < 1536) {
        int jj = j - 512;
        int c = jj >> 8, col = jj & 255;
        const float* p = (c == 0) ? Wr
                       : (c == 1) ? Wl + (size_t)1 * K * 256
                       : (c == 2) ? Wl + (size_t)2 * K * 256
                                  : Wr + (size_t)3 * K * 256;
        return p[(size_t)k * 256 + col];
    }
    int jj = j - 1536;
    return (jj < 256) ? Wr[((size_t)2 * K + k) * 256 + jj]
                      : Wl[((size_t)3 * K + k) * 256 + (jj - 256)];
}

__global__ void prep_weights(const float* __restrict__ lw, const float* __restrict__ ow,
                             const float* __restrict__ wl0, const float* __restrict__ wr0,
                             const float* __restrict__ wl1, const float* __restrict__ wr1,
                             __half* __restrict__ rlinT, __half* __restrict__ routT,
                             __half* __restrict__ cat0T, __half* __restrict__ cat1T)
{
    int i = blockIdx.x * blockDim.x + threadIdx.x;
    if (i < 49152) {            // rlinT [3][n<64][k<256] <- lw[3][k][n]
        int m = i >> 14, r = i & 16383, n = r >> 8, k = r & 255;
        rlinT[i] = __float2half_rn(lw[m * 16384 + k * 64 + n]);
        return;
    }
    i -= 49152;
    if (i < 196608) {           // routT [3][n<256][k<256] <- ow[3][k][n]
        int m = i >> 16, r = i & 65535, n = r >> 8, k = r & 255;
        routT[i] = __float2half_rn(ow[m * 65536 + k * 256 + n]);
        return;
    }
    i -= 196608;
    if (i < 131072) {           // cat0T [2048][64]
        int j = i >> 6, k = i & 63;
        cat0T[i] = __float2half_rn(catT_src(j, k, 64, wl0, wr0));
        return;
    }
    i -= 131072;
    if (i < 524288) {           // cat1T [2048][256]
        int j = i >> 8, k = i & 255;
        cat1T[i] = __float2half_rn(catT_src(j, k, 256, wl1, wr1));
    }
}

// convert raw fp32 x inputs to half (float4 -> 4 halves)
__global__ void conv_x(const float* __restrict__ xt, const float* __restrict__ xc,
                       const float* __restrict__ xf,
                       __half* __restrict__ ht, __half* __restrict__ hc, __half* __restrict__ hf)
{
    const int t4 = NT * 64, c4 = NC * 64, f4 = NF * 64;
    int i = blockIdx.x * blockDim.x + threadIdx.x;
    const float4* src; __half* dst; int j;
    if (i < t4) { src = (const float4*)xt; dst = ht; j = i; }
    else if ((j = i - t4) < c4) { src = (const float4*)xc; dst = hc; }
    else if ((j = i - t4 - c4) < f4) { src = (const float4*)xf; dst = hf; }
    else return;
    float4 v = src[j];
    __half2 h0 = __floats2half2_rn(v.x, v.y);
    __half2 h1 = __floats2half2_rn(v.z, v.w);
    uint2 pack;
    pack.x = *(uint32_t*)&h0;
    pack.y = *(uint32_t*)&h1;
    *(uint2*)(dst + (size_t)j * 4) = pack;
}

// ---------------- CSR build (unchanged, proven) ----------------
struct CsrB {
    const int* dst[4];
    int eStart[5];
    int slotBase[4];
};

__global__ void csr_count(CsrB cb, int* __restrict__ counts)
{
    int i = blockIdx.x * 256 + threadIdx.x;
    if (i >= cb.eStart[4]) return;
    int c = (i >= cb.eStart[2]) ? ((i >= cb.eStart[3]) ? 3 : 2)
                                : ((i >= cb.eStart[1]) ? 1 : 0);
    int e = i - cb.eStart[c];
    atomicAdd(&counts[cb.slotBase[c] + cb.dst[c][e]], 1);
}

__global__ void scan1(const int* __restrict__ cnt, int* __restrict__ incl,
                      int* __restrict__ bsum, int n)
{
    __shared__ int sh[1024];
    int i = blockIdx.x * 1024 + threadIdx.x;
    sh[threadIdx.x] = (i < n) ? cnt[i] : 0;
    __syncthreads();
#pragma unroll
    for (int o = 1; o < 1024; o <<= 1) {
        int t = (threadIdx.x >= o) ? sh[threadIdx.x - o] : 0;
        __syncthreads();
        sh[threadIdx.x] += t;
        __syncthreads();
    }
    if (i < n) incl[i] = sh[threadIdx.x];
    if (threadIdx.x == 1023) bsum[blockIdx.x] = sh[1023];
}

__global__ void scan2(int* __restrict__ bsum, int nb)
{
    __shared__ int sh[1024];
    int t = threadIdx.x;
    sh[t] = (t < nb) ? bsum[t] : 0;
    __syncthreads();
#pragma unroll
    for (int o = 1; o < 1024; o <<= 1) {
        int v = (t >= o) ? sh[t - o] : 0;
        __syncthreads();
        sh[t] += v;
        __syncthreads();
    }
    if (t < nb) bsum[t] = sh[t];
}

__global__ void scan3(const int* __restrict__ cnt, int* __restrict__ ptr,
                      const int* __restrict__ bsum, int n)
{
    int i = blockIdx.x * 1024 + threadIdx.x;
    if (i >= n) return;
    int off = blockIdx.x ? bsum[blockIdx.x - 1] : 0;
    ptr[i] = ptr[i] + off - cnt[i];
}

__global__ void csr_fill(CsrB cb, const int* __restrict__ rowptr,
                         int* __restrict__ cursor, int* __restrict__ perm)
{
    int i = blockIdx.x * 256 + threadIdx.x;
    if (i >= cb.eStart[4]) return;
    int c = (i >= cb.eStart[2]) ? ((i >= cb.eStart[3]) ? 3 : 2)
                                : ((i >= cb.eStart[1]) ? 1 : 0);
    int e = i - cb.eStart[c];
    int slot = cb.slotBase[c] + cb.dst[c][e];
    int pos = atomicAdd(&cursor[slot], 1);
    perm[rowptr[slot] + pos] = e;
}

// ---------------- fused gather (fp32 in, half feature out) ----------------
struct GatherB {
    const int* srcs[4];
    const float* xl[4]; int xls[4];
    const float* xr[4]; int xrs[4];
    const float* att;
    const float* bias;
    const int* rowptr; const int* counts; const int* perm;
    int slotBase[4];
};

__device__ __forceinline__ float eluf(float x) { return x > 0.f ? x : expm1f(x); }

__device__ __forceinline__ void accum_fused(int conv, int slot, int d,
                                            const GatherB& g, float* acc, int lane)
{
    int cnt = g.counts[slot];
    if (cnt == 0) return;
    int start = g.rowptr[slot];

    const float4* pr = (const float4*)(g.xr[conv] + (size_t)d * g.xrs[conv]) + lane * 2;
    float4 r0 = pr[0], r1 = pr[1];
    const float4* pa = (const float4*)(g.att + conv * 256) + lane * 2;
    float4 a0 = pa[0], a1 = pa[1];

    const int* sr = g.srcs[conv];
    const float* xlp = g.xl[conv];
    int stride = g.xls[conv];

    float den = 0.f;
    float num[8];
#pragma unroll
    for (int q = 0; q < 8; q++) num[q] = 0.f;

    for (int j = 0; j < cnt; j++) {
        int e = g.perm[start + j];
        const float4* pl = (const float4*)(xlp + (size_t)sr[e] * stride) + lane * 2;
        float4 l0 = pl[0], l1 = pl[1];
        float t = 0.f, v;
        v = l0.x + r0.x; v = v > 0.f ? v : 0.2f * v; t += v * a0.x;
        v = l0.y + r0.y; v = v > 0.f ? v : 0.2f * v; t += v * a0.y;
        v = l0.z + r0.z; v = v > 0.f ? v : 0.2f * v; t += v * a0.z;
        v = l0.w + r0.w; v = v > 0.f ? v : 0.2f * v; t += v * a0.w;
        v = l1.x + r1.x; v = v > 0.f ? v : 0.2f * v; t += v * a1.x;
        v = l1.y + r1.y; v = v > 0.f ? v : 0.2f * v; t += v * a1.y;
        v = l1.z + r1.z; v = v > 0.f ? v : 0.2f * v; t += v * a1.z;
        v = l1.w + r1.w; v = v > 0.f ? v : 0.2f * v; t += v * a1.w;
        t += __shfl_xor_sync(0xffffffffu, t, 1);
        t += __shfl_xor_sync(0xffffffffu, t, 2);
        t += __shfl_xor_sync(0xffffffffu, t, 4);
        float z = expf(t);
        den += z;
        num[0] += z * l0.x; num[1] += z * l0.y; num[2] += z * l0.z; num[3] += z * l0.w;
        num[4] += z * l1.x; num[5] += z * l1.y; num[6] += z * l1.z; num[7] += z * l1.w;
    }
    float inv = 1.f / den;
#pragma unroll
    for (int q = 0; q < 8; q++) acc[q] += num[q] * inv;
}

__global__ void gather_b(GatherB g, __half* __restrict__ ft, __half* __restrict__ fc,
                         __half* __restrict__ ff)
{
    int r = blockIdx.x * 8 + (threadIdx.x >> 5);
    if (r >= NROWS) return;
    int lane = threadIdx.x & 31;
    float acc[8];
#pragma unroll
    for (int q = 0; q < 8; q++) acc[q] = 0.f;
    __half* out;
    float res[8];
    if (r < NT) {
        accum_fused(1, g.slotBase[1] + r, r, g, acc, lane);
        const float4* pb = (const float4*)(g.bias + 256) + lane * 2;
        float4 b0 = pb[0], b1 = pb[1];
        res[0] = acc[0] + b0.x; res[1] = acc[1] + b0.y; res[2] = acc[2] + b0.z; res[3] = acc[3] + b0.w;
        res[4] = acc[4] + b1.x; res[5] = acc[5] + b1.y; res[6] = acc[6] + b1.z; res[7] = acc[7] + b1.w;
        out = ft + (size_t)r * 256;
    } else if (r < NT + NF) {
        int d = r - NT;
        accum_fused(2, g.slotBase[2] + d, d, g, acc, lane);
        const float4* pb = (const float4*)(g.bias + 512) + lane * 2;
        float4 b0 = pb[0], b1 = pb[1];
        res[0] = acc[0] + b0.x; res[1] = acc[1] + b0.y; res[2] = acc[2] + b0.z; res[3] = acc[3] + b0.w;
        res[4] = acc[4] + b1.x; res[5] = acc[5] + b1.y; res[6] = acc[6] + b1.z; res[7] = acc[7] + b1.w;
        out = ff + (size_t)d * 256;
    } else {
        int d = r - NT - NF;
        accum_fused(0, g.slotBase[0] + d, d, g, acc, lane);
        accum_fused(3, g.slotBase[3] + d, d, g, acc, lane);
        const float4* ph = (const float4*)(g.bias + 0) + lane * 2;
        const float4* pp = (const float4*)(g.bias + 768) + lane * 2;
        float4 h0 = ph[0], h1 = ph[1], p0 = pp[0], p1 = pp[1];
        res[0] = 0.5f * (acc[0] + h0.x + p0.x); res[1] = 0.5f * (acc[1] + h0.y + p0.y);
        res[2] = 0.5f * (acc[2] + h0.z + p0.z); res[3] = 0.5f * (acc[3] + h0.w + p0.w);
        res[4] = 0.5f * (acc[4] + h1.x + p1.x); res[5] = 0.5f * (acc[5] + h1.y + p1.y);
        res[6] = 0.5f * (acc[6] + h1.z + p1.z); res[7] = 0.5f * (acc[7] + h1.w + p1.w);
        out = fc + (size_t)d * 256;
    }
    __half2 hv[4];
#pragma unroll
    for (int q = 0; q < 4; q++)
        hv[q] = __floats2half2_rn(eluf(res[q * 2]), eluf(res[q * 2 + 1]));
    *(uint4*)(out + lane * 8) = *(uint4*)hv;
}

// ---------------- host orchestration ----------------
extern "C" void kernel_launch(void* const* d_in, const int* in_sizes, int n_in,
                              void* d_out, int out_size)
{
    (void)in_sizes; (void)n_in; (void)out_size;
    const float* x_table  = (const float*)d_in[0];
    const float* x_column = (const float*)d_in[1];
    const float* x_fk     = (const float*)d_in[2];
    const float* lin_w    = (const float*)d_in[3];
    const float* lin_b    = (const float*)d_in[4];
    const float* out_w    = (const float*)d_in[5];
    const float* out_b    = (const float*)d_in[6];
    const float* Wl0      = (const float*)d_in[7];
    const float* Wr0      = (const float*)d_in[8];
    const float* att0     = (const float*)d_in[9];
    const float* b0       = (const float*)d_in[10];
    const float* Wl1      = (const float*)d_in[11];
    const float* Wr1      = (const float*)d_in[12];
    const float* att1     = (const float*)d_in[13];
    const float* b1       = (const float*)d_in[14];
    const int* src_hc = (const int*)d_in[15];
    const int* dst_hc = (const int*)d_in[16];
    const int* src_bt = (const int*)d_in[17];
    const int* dst_bt = (const int*)d_in[18];
    const int* src_is = (const int*)d_in[19];
    const int* dst_is = (const int*)d_in[20];
    const int* src_pt = (const int*)d_in[21];
    const int* dst_pt = (const int*)d_in[22];

    cudaFuncSetAttribute((const void*)gemm_h<1, 1, 64, 4, 2>,
                         cudaFuncAttributeMaxDynamicSharedMemorySize, SMEMH_BN64);
    cudaFuncSetAttribute((const void*)gemm_h<0, 0, 128, 2, 4>,
                         cudaFuncAttributeMaxDynamicSharedMemorySize, SMEMH_BN128);

    float* base = nullptr;
    cudaGetSymbolAddress((void**)&base, g_scratch);
    __half* feat_t = (__half*)(base + OFF_FEAT_T);
    __half* feat_c = (__half*)(base + OFF_FEAT_C);
    __half* feat_f = (__half*)(base + OFF_FEAT_F);
    __half* hxt    = (__half*)(base + OFF_HXT);
    __half* hxc    = (__half*)(base + OFF_HXC);
    __half* hxf    = (__half*)(base + OFF_HXF);
    float* xct    = base + OFF_XCT;
    float* xcc    = base + OFF_XCC;
    float* xcf    = base + OFF_XCF;
    int* counts   = (int*)(base + OFF_COUNTS);
    int* cursor   = (int*)(base + OFF_CURSOR);
    int* rowptr   = (int*)(base + OFF_ROWPTR);
    int* bsum     = (int*)(base + OFF_BSUM);
    int* perm     = (int*)(base + OFF_PERM);
    __half* rlinT = (__half*)(base + OFF_RLIN);
    __half* routT = (__half*)(base + OFF_ROUT);
    __half* cat0T = (__half*)(base + OFF_CAT0);
    __half* cat1T = (__half*)(base + OFF_CAT1);

    // 1. prep: weights (half + transpose + concat), x inputs -> half
    prep_weights<<<(901120 + 255) / 256, 256>>>(lin_w, out_w, Wl0, Wr0, Wl1, Wr1,
                                                rlinT, routT, cat0T, cat1T);
    {
        int tot4 = NT * 64 + NC * 64 + NF * 64;
        conv_x<<<(tot4 + 255) / 256, 256>>>(x_table, x_column, x_fk, hxt, hxc, hxf);
    }

    // 2. CSR build
    const int slotBase[4] = {0, NC, NC + NT, NC + NT + NF};
    CsrB cb{};
    cb.dst[0] = dst_hc; cb.dst[1] = dst_bt; cb.dst[2] = dst_is; cb.dst[3] = dst_pt;
    cb.eStart[0] = 0; cb.eStart[1] = E_HC; cb.eStart[2] = E_HC + E_BT;
    cb.eStart[3] = E_HC + E_BT + E_IS; cb.eStart[4] = NEDGES;
    for (int c = 0; c < 4; c++) cb.slotBase[c] = slotBase[c];

    cudaMemsetAsync(counts, 0, (size_t)NSLOTS * 2 * sizeof(int), 0);
    csr_count<<<(NEDGES + 255) / 256, 256>>>(cb, counts);
    const int nScanBlocks = (NSLOTS + 1023) / 1024;
    scan1<<<nScanBlocks, 1024>>>(counts, rowptr, bsum, NSLOTS);
    scan2<<<1, 1024>>>(bsum, nScanBlocks);
    scan3<<<nScanBlocks, 1024>>>(counts, rowptr, bsum, NSLOTS);
    csr_fill<<<(NEDGES + 255) / 256, 256>>>(cb, rowptr, cursor, perm);

    const int bT = (NT + 127) / 128;   // 157
    const int bC = (NC + 127) / 128;   // 1563
    const int bF = (NF + 127) / 128;   // 313

    // 3. input projections (K=256, N=64, lrelu, half out)
    {
        GemmGroups gp{};
        gp.K = 256;
        gp.A[0] = hxt; gp.B[0] = rlinT;          gp.bias[0] = lin_b;       gp.C[0] = feat_t; gp.M[0] = NT; gp.N[0] = 64;
        gp.A[1] = hxc; gp.B[1] = rlinT + 16384;  gp.bias[1] = lin_b + 64;  gp.C[1] = feat_c; gp.M[1] = NC; gp.N[1] = 64;
        gp.A[2] = hxf; gp.B[2] = rlinT + 32768;  gp.bias[2] = lin_b + 128; gp.C[2] = feat_f; gp.M[2] = NF; gp.N[2] = 64;
        for (int g = 0; g < 3; g++) { gp.maskX[g] = 0; gp.shiftX[g] = 0; }
        gp.blockStart[0] = 0; gp.blockStart[1] = bT; gp.blockStart[2] = bT + bC;
        gemm_h<1, 1, 64, 4, 2><<<bT + bC + bF, 256, SMEMH_BN64>>>(gp);
    }

    const int* srcs[4] = {src_hc, src_bt, src_is, src_pt};
    const float* xls[4] = {xct + 0,   xcc + 256, xcc + 512, xcf + 256};
    const int    lss[4] = {512, 1024, 1024, 512};
    const float* xrs[4] = {xcc + 0,   xct + 256, xcf + 0,   xcc + 768};
    const int    rss[4] = {1024, 512, 512, 1024};

    for (int l = 0; l < 2; l++) {
        const int Kin = (l == 0) ? 64 : 256;
        __half* catT = (l == 0) ? cat0T : cat1T;
        const float* att = l ? att1 : att0;
        const float* bb  = l ? b1   : b0;

        // 4. concatenated conv projections (fp32 out)
        {
            GemmGroups gp{};
            gp.K = Kin;
            gp.A[0] = feat_t; gp.B[0] = catT;                     gp.bias[0] = nullptr; gp.C[0] = xct; gp.M[0] = NT; gp.N[0] = 512;
            gp.A[1] = feat_c; gp.B[1] = catT + (size_t)512 * Kin; gp.bias[1] = nullptr; gp.C[1] = xcc; gp.M[1] = NC; gp.N[1] = 1024;
            gp.A[2] = feat_f; gp.B[2] = catT + (size_t)1536 * Kin; gp.bias[2] = nullptr; gp.C[2] = xcf; gp.M[2] = NF; gp.N[2] = 512;
            gp.maskX[0] = 3; gp.shiftX[0] = 2;
            gp.maskX[1] = 7; gp.shiftX[1] = 3;
            gp.maskX[2] = 3; gp.shiftX[2] = 2;
            gp.blockStart[0] = 0;
            gp.blockStart[1] = bT * 4;
            gp.blockStart[2] = bT * 4 + bC * 8;
            gemm_h<0, 0, 128, 2, 4><<<bT * 4 + bC * 8 + bF * 4, 256, SMEMH_BN128>>>(gp);
        }

        // 5. fused gather + ELU/combine epilogue -> half features
        GatherB g{};
        for (int c = 0; c < 4; c++) {
            g.srcs[c] = srcs[c];
            g.xl[c] = xls[c]; g.xls[c] = lss[c];
            g.xr[c] = xrs[c]; g.xrs[c] = rss[c];
            g.slotBase[c] = slotBase[c];
        }
        g.att = att;
        g.bias = bb;
        g.rowptr = rowptr; g.counts = counts; g.perm = perm;
        gather_b<<<(NROWS + 7) / 8, 256>>>(g, feat_t, feat_c, feat_f);
    }

    // 6. output heads (fp32 out -> d_out)
    {
        float* out = (float*)d_out;
        GemmGroups gp{};
        gp.K = 256;
        gp.A[0] = feat_t; gp.B[0] = routT;          gp.bias[0] = out_b;       gp.C[0] = out;                           gp.M[0] = NT; gp.N[0] = 256;
        gp.A[1] = feat_c; gp.B[1] = routT + 65536;  gp.bias[1] = out_b + 256; gp.C[1] = out + (size_t)NT * 256;        gp.M[1] = NC; gp.N[1] = 256;
        gp.A[2] = feat_f; gp.B[2] = routT + 131072; gp.bias[2] = out_b + 512; gp.C[2] = out + (size_t)(NT + NC) * 256; gp.M[2] = NF; gp.N[2] = 256;
        for (int g = 0; g < 3; g++) { gp.maskX[g] = 1; gp.shiftX[g] = 1; }
        gp.blockStart[0] = 0; gp.blockStart[1] = bT * 2; gp.blockStart[2] = bT * 2 + bC * 2;
        gemm_h<0, 0, 128, 2, 4><<<(bT + bC + bF) * 2, 256, SMEMH_BN128>>>(gp);
    }
}

// round 17
// speedup vs baseline: 2.1989x; 1.0289x over previous
#include <cuda_runtime.h>
#include <cuda_fp16.h>
#include <math.h>
#include <stdint.h>

// ---------------- problem constants ----------------
#define NT 20000
#define NC 200000
#define NF 40000
#define E_HC 200000
#define E_BT 200000
#define E_IS 80000
#define E_PT 80000
#define FH 256
#define NSLOTS (NC + NT + NF + NC)
#define NEDGES (E_HC + E_BT + E_IS + E_PT)
#define NROWS (NT + NF + NC)

// ---------------- scratch offsets (float units) ----------------
// half regions occupy count/2 float slots; all offsets 16B-aligned.
static constexpr size_t OFF_FEAT_T = 0;                                   // half NT*256
static constexpr size_t OFF_FEAT_C = OFF_FEAT_T + (size_t)NT * 128;
static constexpr size_t OFF_FEAT_F = OFF_FEAT_C + (size_t)NC * 128;
static constexpr size_t OFF_HXT    = OFF_FEAT_F + (size_t)NF * 128;
static constexpr size_t OFF_HXC    = OFF_HXT + (size_t)NT * 128;
static constexpr size_t OFF_HXF    = OFF_HXC + (size_t)NC * 128;
static constexpr size_t OFF_XCT    = OFF_HXF + (size_t)NF * 128;         // half NT x 512
static constexpr size_t OFF_XCC    = OFF_XCT + (size_t)NT * 256;         // half NC x 1024
static constexpr size_t OFF_XCF    = OFF_XCC + (size_t)NC * 512;         // half NF x 512
static constexpr size_t OFF_COUNTS = OFF_XCF + (size_t)NF * 256;
static constexpr size_t OFF_CURSOR = OFF_COUNTS + NSLOTS;
static constexpr size_t OFF_ROWPTR = OFF_CURSOR + NSLOTS;
static constexpr size_t OFF_BSUM   = OFF_ROWPTR + NSLOTS;
static constexpr size_t OFF_PERM   = OFF_BSUM + 1024;
static constexpr size_t OFF_RLIN   = OFF_PERM + NEDGES;                  // half 49152
static constexpr size_t OFF_ROUT   = OFF_RLIN + 24576;                   // half 196608
static constexpr size_t OFF_CAT0   = OFF_ROUT + 98304;                   // half 131072
static constexpr size_t OFF_CAT1   = OFF_CAT0 + 65536;                   // half 524288
static constexpr size_t SCRATCH_TOTAL = OFF_CAT1 + 262144;

__device__ float g_scratch[SCRATCH_TOTAL];

// ---------------- PTX helpers ----------------
__device__ __forceinline__ void cp_async16(void* dst, const void* src)
{
    uint32_t d = (uint32_t)__cvta_generic_to_shared(dst);
    asm volatile("cp.async.cg.shared.global [%0], [%1], 16;\n" :: "r"(d), "l"(src));
}
__device__ __forceinline__ void cp_commit() { asm volatile("cp.async.commit_group;\n" ::: "memory"); }
__device__ __forceinline__ void cp_wait0()  { asm volatile("cp.async.wait_group 0;\n" ::: "memory"); }
__device__ __forceinline__ void cp_wait1()  { asm volatile("cp.async.wait_group 1;\n" ::: "memory"); }

__device__ __forceinline__ void mma_f16(float* c, const uint32_t* a, const uint32_t* b)
{
    asm volatile("mma.sync.aligned.m16n8k16.row.col.f32.f16.f16.f32 "
                 "{%0,%1,%2,%3}, {%4,%5,%6,%7}, {%8,%9}, {%0,%1,%2,%3};"
                 : "+f"(c[0]), "+f"(c[1]), "+f"(c[2]), "+f"(c[3])
                 : "r"(a[0]), "r"(a[1]), "r"(a[2]), "r"(a[3]), "r"(b[0]), "r"(b[1]));
}

// ---------------- grouped fp16 GEMM ----------------
// A [M,K] half row-major. B [N,K] half row-major (K-contiguous).
// acc fp32. Output fp32 (OUT_HALF=0) or half (OUT_HALF=1), optional lrelu.
struct GemmGroups {
    const __half* A[3]; const __half* B[3]; const float* bias[3]; void* C[3];
    int M[3]; int N[3];
    int maskX[3]; int shiftX[3];
    int blockStart[3];
    int K;
};

template<int ACT, int OUT_HALF, int BN, int WARPS_M, int WARPS_N>
__global__ void __launch_bounds__(256, 2)
gemm_h(GemmGroups gg)
{
    constexpr int BM = 128, BK = 32;
    constexpr int BKP = 40;   // halves; 80B row stride -> conflict-free
    constexpr int WM = BM / WARPS_M, WN = BN / WARPS_N;
    constexpr int MI = WM / 16, NI = WN / 8;
    constexpr int A_STAGE = BM * BKP;
    constexpr int B_STAGE = BN * BKP;
    constexpr int STAGES = 3;

    extern __shared__ __half smh[];
    __half* Asm = smh;
    __half* Bsm = smh + STAGES * A_STAGE;

    const int bid = blockIdx.x;
    const int g = (bid >= gg.blockStart[1]) + (bid >= gg.blockStart[2]);
    const int local = bid - gg.blockStart[g];
    const int tileX = local & gg.maskX[g];
    const int tileY = local >> gg.shiftX[g];

    const __half* __restrict__ A = gg.A[g];
    const __half* __restrict__ Bt = gg.B[g];
    const float* __restrict__ bias = gg.bias[g];
    const int M = gg.M[g], N = gg.N[g], K = gg.K;
    const int rowBase = tileY * BM;
    const int colBase = tileX * BN;

    const int tid  = threadIdx.x;
    const int lane = tid & 31;
    const int warp = tid >> 5;
    const int gq   = lane >> 2;
    const int tig  = lane & 3;
    const int warpM = warp % WARPS_M;
    const int warpN = warp / WARPS_M;

    float acc[MI][NI][4];
#pragma unroll
    for (int mi = 0; mi < MI; mi++)
#pragma unroll
        for (int ni = 0; ni < NI; ni++)
#pragma unroll
            for (int q = 0; q < 4; q++) acc[mi][ni][q] = 0.f;

    auto load_tile = [&](int t, int s) {
#pragma unroll
        for (int i = 0; i < 2; i++) {
            int li = tid + i * 256;
            int m = li >> 2;
            int c8 = (li & 3) << 3;
            int gm = rowBase + m;
            if (gm >= M) gm = M - 1;
            cp_async16(Asm + s * A_STAGE + m * BKP + c8,
                       A + (size_t)gm * K + t * BK + c8);
        }
#pragma unroll
        for (int i = 0; i < BN / 64; i++) {
            int li = tid + i * 256;
            int n = li >> 2;
            int c8 = (li & 3) << 3;
            cp_async16(Bsm + s * B_STAGE + n * BKP + c8,
                       Bt + (size_t)(colBase + n) * K + t * BK + c8);
        }
        cp_commit();
    };

    const int nT = K / BK;
    load_tile(0, 0);
    if (nT > 1) load_tile(1, 1);

    for (int t = 0; t < nT; t++) {
        if (t + 1 < nT) cp_wait1(); else cp_wait0();
        __syncthreads();
        if (t + 2 < nT) load_tile(t + 2, (t + 2) % STAGES);

        const __half* Asb = Asm + (t % STAGES) * A_STAGE;
        const __half* Bsb = Bsm + (t % STAGES) * B_STAGE;
#pragma unroll
        for (int k16 = 0; k16 < BK / 16; k16++) {
            const int kk = k16 * 16;
            uint32_t a[MI][4], b[NI][2];
#pragma unroll
            for (int mi = 0; mi < MI; mi++) {
                const __half* ap = Asb + (warpM * WM + mi * 16 + gq) * BKP + kk + 2 * tig;
                a[mi][0] = *(const uint32_t*)(ap);
                a[mi][1] = *(const uint32_t*)(ap + 8 * BKP);
                a[mi][2] = *(const uint32_t*)(ap + 8);
                a[mi][3] = *(const uint32_t*)(ap + 8 * BKP + 8);
            }
#pragma unroll
            for (int ni = 0; ni < NI; ni++) {
                const __half* bp = Bsb + (warpN * WN + ni * 8 + gq) * BKP + kk + 2 * tig;
                b[ni][0] = *(const uint32_t*)(bp);
                b[ni][1] = *(const uint32_t*)(bp + 8);
            }
#pragma unroll
            for (int mi = 0; mi < MI; mi++)
#pragma unroll
                for (int ni = 0; ni < NI; ni++)
                    mma_f16(acc[mi][ni], a[mi], b[ni]);
        }
    }

#pragma unroll
    for (int mi = 0; mi < MI; mi++) {
        int row0 = rowBase + warpM * WM + mi * 16 + gq;
#pragma unroll
        for (int ni = 0; ni < NI; ni++) {
            int col = colBase + warpN * WN + ni * 8 + tig * 2;
            float bx = 0.f, by = 0.f;
            if (bias) { bx = bias[col]; by = bias[col + 1]; }
#pragma unroll
            for (int h = 0; h < 2; h++) {
                int row = row0 + h * 8;
                float2 v;
                v.x = acc[mi][ni][h * 2 + 0] + bx;
                v.y = acc[mi][ni][h * 2 + 1] + by;
                if (ACT == 1) {
                    v.x = v.x > 0.f ? v.x : 0.01f * v.x;
                    v.y = v.y > 0.f ? v.y : 0.01f * v.y;
                }
                if (row < M) {
                    if (OUT_HALF) {
                        __half2 hv = __floats2half2_rn(v.x, v.y);
                        *(__half2*)((__half*)gg.C[g] + (size_t)row * N + col) = hv;
                    } else {
                        *(float2*)((float*)gg.C[g] + (size_t)row * N + col) = v;
                    }
                }
            }
        }
    }
}

#define SMEMH_BN128 (3 * (128*40 + 128*40) * 2)   // 61440
#define SMEMH_BN64  (3 * (128*40 + 64*40)  * 2)   // 46080

// ---------------- weight prep: half + transpose + concat ----------------
__device__ float catT_src(int j, int k, int K, const float* Wl, const float* Wr)
{
    if (j < 512) {
        return (j < 256) ? Wl[(size_t)k * 256 + j]
                         : Wr[((size_t)K + k) * 256 + (j - 256)];
    }
    if (j < 1536) {
        int jj = j - 512;
        int c = jj >> 8, col = jj & 255;
        const float* p = (c == 0) ? Wr
                       : (c == 1) ? Wl + (size_t)1 * K * 256
                       : (c == 2) ? Wl + (size_t)2 * K * 256
                                  : Wr + (size_t)3 * K * 256;
        return p[(size_t)k * 256 + col];
    }
    int jj = j - 1536;
    return (jj < 256) ? Wr[((size_t)2 * K + k) * 256 + jj]
                      : Wl[((size_t)3 * K + k) * 256 + (jj - 256)];
}

__global__ void prep_weights(const float* __restrict__ lw, const float* __restrict__ ow,
                             const float* __restrict__ wl0, const float* __restrict__ wr0,
                             const float* __restrict__ wl1, const float* __restrict__ wr1,
                             __half* __restrict__ rlinT, __half* __restrict__ routT,
                             __half* __restrict__ cat0T, __half* __restrict__ cat1T)
{
    int i = blockIdx.x * blockDim.x + threadIdx.x;
    if (i < 49152) {
        int m = i >> 14, r = i & 16383, n = r >> 8, k = r & 255;
        rlinT[i] = __float2half_rn(lw[m * 16384 + k * 64 + n]);
        return;
    }
    i -= 49152;
    if (i < 196608) {
        int m = i >> 16, r = i & 65535, n = r >> 8, k = r & 255;
        routT[i] = __float2half_rn(ow[m * 65536 + k * 256 + n]);
        return;
    }
    i -= 196608;
    if (i < 131072) {
        int j = i >> 6, k = i & 63;
        cat0T[i] = __float2half_rn(catT_src(j, k, 64, wl0, wr0));
        return;
    }
    i -= 131072;
    if (i < 524288) {
        int j = i >> 8, k = i & 255;
        cat1T[i] = __float2half_rn(catT_src(j, k, 256, wl1, wr1));
    }
}

// convert raw fp32 x inputs to half
__global__ void conv_x(const float* __restrict__ xt, const float* __restrict__ xc,
                       const float* __restrict__ xf,
                       __half* __restrict__ ht, __half* __restrict__ hc, __half* __restrict__ hf)
{
    const int t4 = NT * 64, c4 = NC * 64, f4 = NF * 64;
    int i = blockIdx.x * blockDim.x + threadIdx.x;
    const float4* src; __half* dst; int j;
    if (i < t4) { src = (const float4*)xt; dst = ht; j = i; }
    else if ((j = i - t4) < c4) { src = (const float4*)xc; dst = hc; }
    else if ((j = i - t4 - c4) < f4) { src = (const float4*)xf; dst = hf; }
    else return;
    float4 v = src[j];
    __half2 h0 = __floats2half2_rn(v.x, v.y);
    __half2 h1 = __floats2half2_rn(v.z, v.w);
    uint2 pack;
    pack.x = *(uint32_t*)&h0;
    pack.y = *(uint32_t*)&h1;
    *(uint2*)(dst + (size_t)j * 4) = pack;
}

// ---------------- CSR build (unchanged, proven) ----------------
struct CsrB {
    const int* dst[4];
    int eStart[5];
    int slotBase[4];
};

__global__ void csr_count(CsrB cb, int* __restrict__ counts)
{
    int i = blockIdx.x * 256 + threadIdx.x;
    if (i >= cb.eStart[4]) return;
    int c = (i >= cb.eStart[2]) ? ((i >= cb.eStart[3]) ? 3 : 2)
                                : ((i >= cb.eStart[1]) ? 1 : 0);
    int e = i - cb.eStart[c];
    atomicAdd(&counts[cb.slotBase[c] + cb.dst[c][e]], 1);
}

__global__ void scan1(const int* __restrict__ cnt, int* __restrict__ incl,
                      int* __restrict__ bsum, int n)
{
    __shared__ int sh[1024];
    int i = blockIdx.x * 1024 + threadIdx.x;
    sh[threadIdx.x] = (i < n) ? cnt[i] : 0;
    __syncthreads();
#pragma unroll
    for (int o = 1; o < 1024; o <<= 1) {
        int t = (threadIdx.x >= o) ? sh[threadIdx.x - o] : 0;
        __syncthreads();
        sh[threadIdx.x] += t;
        __syncthreads();
    }
    if (i < n) incl[i] = sh[threadIdx.x];
    if (threadIdx.x == 1023) bsum[blockIdx.x] = sh[1023];
}

__global__ void scan2(int* __restrict__ bsum, int nb)
{
    __shared__ int sh[1024];
    int t = threadIdx.x;
    sh[t] = (t < nb) ? bsum[t] : 0;
    __syncthreads();
#pragma unroll
    for (int o = 1; o < 1024; o <<= 1) {
        int v = (t >= o) ? sh[t - o] : 0;
        __syncthreads();
        sh[t] += v;
        __syncthreads();
    }
    if (t < nb) bsum[t] = sh[t];
}

__global__ void scan3(const int* __restrict__ cnt, int* __restrict__ ptr,
                      const int* __restrict__ bsum, int n)
{
    int i = blockIdx.x * 1024 + threadIdx.x;
    if (i >= n) return;
    int off = blockIdx.x ? bsum[blockIdx.x - 1] : 0;
    ptr[i] = ptr[i] + off - cnt[i];
}

__global__ void csr_fill(CsrB cb, const int* __restrict__ rowptr,
                         int* __restrict__ cursor, int* __restrict__ perm)
{
    int i = blockIdx.x * 256 + threadIdx.x;
    if (i >= cb.eStart[4]) return;
    int c = (i >= cb.eStart[2]) ? ((i >= cb.eStart[3]) ? 3 : 2)
                                : ((i >= cb.eStart[1]) ? 1 : 0);
    int e = i - cb.eStart[c];
    int slot = cb.slotBase[c] + cb.dst[c][e];
    int pos = atomicAdd(&cursor[slot], 1);
    perm[rowptr[slot] + pos] = e;
}

// ---------------- fused gather (half projections in, half feature out) ----
struct GatherB {
    const int* srcs[4];
    const __half* xl[4]; int xls[4];   // strides in halves
    const __half* xr[4]; int xrs[4];
    const float* att;
    const float* bias;
    const int* rowptr; const int* counts; const int* perm;
    int slotBase[4];
};

__device__ __forceinline__ float eluf(float x) { return x > 0.f ? x : expm1f(x); }

__device__ __forceinline__ void unpack8(uint4 v, float* f)
{
    float2 t;
    t = __half22float2(*(__half2*)&v.x); f[0] = t.x; f[1] = t.y;
    t = __half22float2(*(__half2*)&v.y); f[2] = t.x; f[3] = t.y;
    t = __half22float2(*(__half2*)&v.z); f[4] = t.x; f[5] = t.y;
    t = __half22float2(*(__half2*)&v.w); f[6] = t.x; f[7] = t.y;
}

__device__ __forceinline__ void accum_fused(int conv, int slot, int d,
                                            const GatherB& g, float* acc, int lane)
{
    int cnt = g.counts[slot];
    if (cnt == 0) return;
    int start = g.rowptr[slot];

    uint4 rv = *((const uint4*)(g.xr[conv] + (size_t)d * g.xrs[conv]) + lane);
    float r[8]; unpack8(rv, r);
    const float4* pa = (const float4*)(g.att + conv * 256) + lane * 2;
    float4 a0 = pa[0], a1 = pa[1];
    float aatt[8] = {a0.x, a0.y, a0.z, a0.w, a1.x, a1.y, a1.z, a1.w};

    const int* sr = g.srcs[conv];
    const __half* xlp = g.xl[conv];
    int stride = g.xls[conv];

    float den = 0.f;
    float num[8];
#pragma unroll
    for (int q = 0; q < 8; q++) num[q] = 0.f;

    for (int j = 0; j < cnt; j++) {
        int e = g.perm[start + j];
        uint4 lv = *((const uint4*)(xlp + (size_t)sr[e] * stride) + lane);
        float l[8]; unpack8(lv, l);
        float t = 0.f;
#pragma unroll
        for (int q = 0; q < 8; q++) {
            float v = l[q] + r[q];
            v = v > 0.f ? v : 0.2f * v;
            t += v * aatt[q];
        }
        t += __shfl_xor_sync(0xffffffffu, t, 1);
        t += __shfl_xor_sync(0xffffffffu, t, 2);
        t += __shfl_xor_sync(0xffffffffu, t, 4);   // full head logit in all 8 lanes
        float z = expf(t);
        den += z;
#pragma unroll
        for (int q = 0; q < 8; q++) num[q] += z * l[q];
    }
    float inv = 1.f / den;
#pragma unroll
    for (int q = 0; q < 8; q++) acc[q] += num[q] * inv;
}

__global__ void gather_b(GatherB g, __half* __restrict__ ft, __half* __restrict__ fc,
                         __half* __restrict__ ff)
{
    int r = blockIdx.x * 8 + (threadIdx.x >> 5);
    if (r >= NROWS) return;
    int lane = threadIdx.x & 31;
    float acc[8];
#pragma unroll
    for (int q = 0; q < 8; q++) acc[q] = 0.f;
    __half* out;
    float res[8];
    if (r < NT) {
        accum_fused(1, g.slotBase[1] + r, r, g, acc, lane);
        const float4* pb = (const float4*)(g.bias + 256) + lane * 2;
        float4 b0 = pb[0], b1 = pb[1];
        res[0] = acc[0] + b0.x; res[1] = acc[1] + b0.y; res[2] = acc[2] + b0.z; res[3] = acc[3] + b0.w;
        res[4] = acc[4] + b1.x; res[5] = acc[5] + b1.y; res[6] = acc[6] + b1.z; res[7] = acc[7] + b1.w;
        out = ft + (size_t)r * 256;
    } else if (r < NT + NF) {
        int d = r - NT;
        accum_fused(2, g.slotBase[2] + d, d, g, acc, lane);
        const float4* pb = (const float4*)(g.bias + 512) + lane * 2;
        float4 b0 = pb[0], b1 = pb[1];
        res[0] = acc[0] + b0.x; res[1] = acc[1] + b0.y; res[2] = acc[2] + b0.z; res[3] = acc[3] + b0.w;
        res[4] = acc[4] + b1.x; res[5] = acc[5] + b1.y; res[6] = acc[6] + b1.z; res[7] = acc[7] + b1.w;
        out = ff + (size_t)d * 256;
    } else {
        int d = r - NT - NF;
        accum_fused(0, g.slotBase[0] + d, d, g, acc, lane);
        accum_fused(3, g.slotBase[3] + d, d, g, acc, lane);
        const float4* ph = (const float4*)(g.bias + 0) + lane * 2;
        const float4* pp = (const float4*)(g.bias + 768) + lane * 2;
        float4 h0 = ph[0], h1 = ph[1], p0 = pp[0], p1 = pp[1];
        res[0] = 0.5f * (acc[0] + h0.x + p0.x); res[1] = 0.5f * (acc[1] + h0.y + p0.y);
        res[2] = 0.5f * (acc[2] + h0.z + p0.z); res[3] = 0.5f * (acc[3] + h0.w + p0.w);
        res[4] = 0.5f * (acc[4] + h1.x + p1.x); res[5] = 0.5f * (acc[5] + h1.y + p1.y);
        res[6] = 0.5f * (acc[6] + h1.z + p1.z); res[7] = 0.5f * (acc[7] + h1.w + p1.w);
        out = fc + (size_t)d * 256;
    }
    __half2 hv[4];
#pragma unroll
    for (int q = 0; q < 4; q++)
        hv[q] = __floats2half2_rn(eluf(res[q * 2]), eluf(res[q * 2 + 1]));
    *(uint4*)(out + lane * 8) = *(uint4*)hv;
}

// ---------------- host orchestration ----------------
extern "C" void kernel_launch(void* const* d_in, const int* in_sizes, int n_in,
                              void* d_out, int out_size)
{
    (void)in_sizes; (void)n_in; (void)out_size;
    const float* x_table  = (const float*)d_in[0];
    const float* x_column = (const float*)d_in[1];
    const float* x_fk     = (const float*)d_in[2];
    const float* lin_w    = (const float*)d_in[3];
    const float* lin_b    = (const float*)d_in[4];
    const float* out_w    = (const float*)d_in[5];
    const float* out_b    = (const float*)d_in[6];
    const float* Wl0      = (const float*)d_in[7];
    const float* Wr0      = (const float*)d_in[8];
    const float* att0     = (const float*)d_in[9];
    const float* b0       = (const float*)d_in[10];
    const float* Wl1      = (const float*)d_in[11];
    const float* Wr1      = (const float*)d_in[12];
    const float* att1     = (const float*)d_in[13];
    const float* b1       = (const float*)d_in[14];
    const int* src_hc = (const int*)d_in[15];
    const int* dst_hc = (const int*)d_in[16];
    const int* src_bt = (const int*)d_in[17];
    const int* dst_bt = (const int*)d_in[18];
    const int* src_is = (const int*)d_in[19];
    const int* dst_is = (const int*)d_in[20];
    const int* src_pt = (const int*)d_in[21];
    const int* dst_pt = (const int*)d_in[22];

    cudaFuncSetAttribute((const void*)gemm_h<1, 1, 64, 4, 2>,
                         cudaFuncAttributeMaxDynamicSharedMemorySize, SMEMH_BN64);
    cudaFuncSetAttribute((const void*)gemm_h<0, 1, 128, 2, 4>,
                         cudaFuncAttributeMaxDynamicSharedMemorySize, SMEMH_BN128);
    cudaFuncSetAttribute((const void*)gemm_h<0, 0, 128, 2, 4>,
                         cudaFuncAttributeMaxDynamicSharedMemorySize, SMEMH_BN128);

    float* base = nullptr;
    cudaGetSymbolAddress((void**)&base, g_scratch);
    __half* feat_t = (__half*)(base + OFF_FEAT_T);
    __half* feat_c = (__half*)(base + OFF_FEAT_C);
    __half* feat_f = (__half*)(base + OFF_FEAT_F);
    __half* hxt    = (__half*)(base + OFF_HXT);
    __half* hxc    = (__half*)(base + OFF_HXC);
    __half* hxf    = (__half*)(base + OFF_HXF);
    __half* xct    = (__half*)(base + OFF_XCT);
    __half* xcc    = (__half*)(base + OFF_XCC);
    __half* xcf    = (__half*)(base + OFF_XCF);
    int* counts   = (int*)(base + OFF_COUNTS);
    int* cursor   = (int*)(base + OFF_CURSOR);
    int* rowptr   = (int*)(base + OFF_ROWPTR);
    int* bsum     = (int*)(base + OFF_BSUM);
    int* perm     = (int*)(base + OFF_PERM);
    __half* rlinT = (__half*)(base + OFF_RLIN);
    __half* routT = (__half*)(base + OFF_ROUT);
    __half* cat0T = (__half*)(base + OFF_CAT0);
    __half* cat1T = (__half*)(base + OFF_CAT1);

    // 1. prep: weights (half + transpose + concat), x inputs -> half
    prep_weights<<<(901120 + 255) / 256, 256>>>(lin_w, out_w, Wl0, Wr0, Wl1, Wr1,
                                                rlinT, routT, cat0T, cat1T);
    {
        int tot4 = NT * 64 + NC * 64 + NF * 64;
        conv_x<<<(tot4 + 255) / 256, 256>>>(x_table, x_column, x_fk, hxt, hxc, hxf);
    }

    // 2. CSR build
    const int slotBase[4] = {0, NC, NC + NT, NC + NT + NF};
    CsrB cb{};
    cb.dst[0] = dst_hc; cb.dst[1] = dst_bt; cb.dst[2] = dst_is; cb.dst[3] = dst_pt;
    cb.eStart[0] = 0; cb.eStart[1] = E_HC; cb.eStart[2] = E_HC + E_BT;
    cb.eStart[3] = E_HC + E_BT + E_IS; cb.eStart[4] = NEDGES;
    for (int c = 0; c < 4; c++) cb.slotBase[c] = slotBase[c];

    cudaMemsetAsync(counts, 0, (size_t)NSLOTS * 2 * sizeof(int), 0);
    csr_count<<<(NEDGES + 255) / 256, 256>>>(cb, counts);
    const int nScanBlocks = (NSLOTS + 1023) / 1024;
    scan1<<<nScanBlocks, 1024>>>(counts, rowptr, bsum, NSLOTS);
    scan2<<<1, 1024>>>(bsum, nScanBlocks);
    scan3<<<nScanBlocks, 1024>>>(counts, rowptr, bsum, NSLOTS);
    csr_fill<<<(NEDGES + 255) / 256, 256>>>(cb, rowptr, cursor, perm);

    const int bT = (NT + 127) / 128;   // 157
    const int bC = (NC + 127) / 128;   // 1563
    const int bF = (NF + 127) / 128;   // 313

    // 3. input projections (K=256, N=64, lrelu, half out)
    {
        GemmGroups gp{};
        gp.K = 256;
        gp.A[0] = hxt; gp.B[0] = rlinT;          gp.bias[0] = lin_b;       gp.C[0] = feat_t; gp.M[0] = NT; gp.N[0] = 64;
        gp.A[1] = hxc; gp.B[1] = rlinT + 16384;  gp.bias[1] = lin_b + 64;  gp.C[1] = feat_c; gp.M[1] = NC; gp.N[1] = 64;
        gp.A[2] = hxf; gp.B[2] = rlinT + 32768;  gp.bias[2] = lin_b + 128; gp.C[2] = feat_f; gp.M[2] = NF; gp.N[2] = 64;
        for (int g = 0; g < 3; g++) { gp.maskX[g] = 0; gp.shiftX[g] = 0; }
        gp.blockStart[0] = 0; gp.blockStart[1] = bT; gp.blockStart[2] = bT + bC;
        gemm_h<1, 1, 64, 4, 2><<<bT + bC + bF, 256, SMEMH_BN64>>>(gp);
    }

    const int* srcs[4] = {src_hc, src_bt, src_is, src_pt};
    const __half* xls[4] = {xct + 0,   xcc + 256, xcc + 512, xcf + 256};
    const int     lss[4] = {512, 1024, 1024, 512};
    const __half* xrs[4] = {xcc + 0,   xct + 256, xcf + 0,   xcc + 768};
    const int     rss[4] = {1024, 512, 512, 1024};

    for (int l = 0; l < 2; l++) {
        const int Kin = (l == 0) ? 64 : 256;
        __half* catT = (l == 0) ? cat0T : cat1T;
        const float* att = l ? att1 : att0;
        const float* bb  = l ? b1   : b0;

        // 4. concatenated conv projections (half out)
        {
            GemmGroups gp{};
            gp.K = Kin;
            gp.A[0] = feat_t; gp.B[0] = catT;                      gp.bias[0] = nullptr; gp.C[0] = xct; gp.M[0] = NT; gp.N[0] = 512;
            gp.A[1] = feat_c; gp.B[1] = catT + (size_t)512 * Kin;  gp.bias[1] = nullptr; gp.C[1] = xcc; gp.M[1] = NC; gp.N[1] = 1024;
            gp.A[2] = feat_f; gp.B[2] = catT + (size_t)1536 * Kin; gp.bias[2] = nullptr; gp.C[2] = xcf; gp.M[2] = NF; gp.N[2] = 512;
            gp.maskX[0] = 3; gp.shiftX[0] = 2;
            gp.maskX[1] = 7; gp.shiftX[1] = 3;
            gp.maskX[2] = 3; gp.shiftX[2] = 2;
            gp.blockStart[0] = 0;
            gp.blockStart[1] = bT * 4;
            gp.blockStart[2] = bT * 4 + bC * 8;
            gemm_h<0, 1, 128, 2, 4><<<bT * 4 + bC * 8 + bF * 4, 256, SMEMH_BN128>>>(gp);
        }

        // 5. fused gather + ELU/combine epilogue -> half features
        GatherB g{};
        for (int c = 0; c < 4; c++) {
            g.srcs[c] = srcs[c];
            g.xl[c] = xls[c]; g.xls[c] = lss[c];
            g.xr[c] = xrs[c]; g.xrs[c] = rss[c];
            g.slotBase[c] = slotBase[c];
        }
        g.att = att;
        g.bias = bb;
        g.rowptr = rowptr; g.counts = counts; g.perm = perm;
        gather_b<<<(NROWS + 7) / 8, 256>>>(g, feat_t, feat_c, feat_f);
    }

    // 6. output heads (fp32 out -> d_out)
    {
        float* out = (float*)d_out;
        GemmGroups gp{};
        gp.K = 256;
        gp.A[0] = feat_t; gp.B[0] = routT;          gp.bias[0] = out_b;       gp.C[0] = out;                           gp.M[0] = NT; gp.N[0] = 256;
        gp.A[1] = feat_c; gp.B[1] = routT + 65536;  gp.bias[1] = out_b + 256; gp.C[1] = out + (size_t)NT * 256;        gp.M[1] = NC; gp.N[1] = 256;
        gp.A[2] = feat_f; gp.B[2] = routT + 131072; gp.bias[2] = out_b + 512; gp.C[2] = out + (size_t)(NT + NC) * 256; gp.M[2] = NF; gp.N[2] = 256;
        for (int g = 0; g < 3; g++) { gp.maskX[g] = 1; gp.shiftX[g] = 1; }
        gp.blockStart[0] = 0; gp.blockStart[1] = bT * 2; gp.blockStart[2] = bT * 2 + bC * 2;
        gemm_h<0, 0, 128, 2, 4><<<(bT + bC + bF) * 2, 256, SMEMH_BN128>>>(gp);
    }
}